// round 12
// baseline (speedup 1.0000x reference)
#include <cuda_runtime.h>
#include <math.h>
#include <stdint.h>

// Problem constants (fixed by the reference)
#define B_   16
#define E_   1024
#define DIN_ 128
#define P_   2048
#define D_   128
#define LMAX 16
#define G3   384   // 3*D
#define PROJ_STRIDE 512   // gate-interleaved proj row: [e*4 + {z,r,h,pad}]

// ---------------- scratch (device globals: no allocations allowed) ---------
__device__ int      g_lut[P_ * LMAX];                          // path+1 per (p,t), 0 if empty (BSS zero)
__device__ float    g_proj[((size_t)B_ * E_ + 1) * PROJ_STRIDE];  // interleaved proj; row 16384 = zero row
__device__ float    g_wkqT[D_ * D_];                           // g_wkqT[dp*128+d] = (WkWq^T)[d][dp]
__device__ float    g_hs[(size_t)B_ * P_ * LMAX * D_];         // GRU hidden states (fp32)
__device__ uint32_t g_wrec[G3 * D_];                           // W_rec^T tf32 quad-fragment image
__device__ uint32_t g_win[G3 * D_];                            // W_in^T  tf32 quad-fragment image

__device__ __forceinline__ float tanha(float x) {
    float r; asm("tanh.approx.f32 %0, %1;" : "=f"(r) : "f"(x)); return r;
}
__device__ __forceinline__ float sigf(float x) { return fmaf(tanha(0.5f * x), 0.5f, 0.5f); }

__device__ __forceinline__ uint32_t f2tf32(float v) {
    uint32_t r;
    asm("cvt.rna.tf32.f32 %0, %1;" : "=r"(r) : "f"(v));
    return r;
}

// quad-fragment word offset within a 128-word row image:
//   off(n,k) = 16*((k>>4)^(n&3)) + 4*(k&3) + 2*((k>>3)&1) + ((k>>2)&1)
__device__ __forceinline__ int quad_off(int n, int k) {
    return 16 * (((k >> 4)) ^ (n & 3)) + 4 * (k & 3) + 2 * ((k >> 3) & 1) + ((k >> 2) & 1);
}

// mma.sync m16n8k8 tf32: D += A*B (fp32 accum)
__device__ __forceinline__ void mma8(float* c, uint32_t a0, uint32_t a1, uint32_t a2, uint32_t a3,
                                     uint32_t b0, uint32_t b1) {
    asm volatile("mma.sync.aligned.m16n8k8.row.col.f32.tf32.tf32.f32 "
                 "{%0,%1,%2,%3}, {%4,%5,%6,%7}, {%8,%9}, {%0,%1,%2,%3};"
                 : "+f"(c[0]), "+f"(c[1]), "+f"(c[2]), "+f"(c[3])
                 : "r"(a0), "r"(a1), "r"(a2), "r"(a3), "r"(b0), "r"(b1));
}

__device__ __forceinline__ float4 shfl4(float4 v, int src) {
    float4 r;
    r.x = __shfl_sync(0xffffffffu, v.x, src);
    r.y = __shfl_sync(0xffffffffu, v.y, src);
    r.z = __shfl_sync(0xffffffffu, v.z, src);
    r.w = __shfl_sync(0xffffffffu, v.w, src);
    return r;
}

// ---------------- setup kernels ---------------------------------------------
__global__ void k_lut_fill(const int* __restrict__ paths, const int* __restrict__ idx,
                           const int* __restrict__ seqs, int T) {
    int j = blockIdx.x * blockDim.x + threadIdx.x;
    if (j < T) g_lut[idx[j] * LMAX + seqs[j]] = paths[j] + 1;
}

// blocks [0,128)=W_rec image, [128,256)=W_in image, [256,299)=wkq, 299=bias0
__global__ void __launch_bounds__(384, 2)
k_prep(const float* __restrict__ bin, const float* __restrict__ brec,
       const float* __restrict__ wk,  const float* __restrict__ wq,
       const float* __restrict__ Wrec, const float* __restrict__ Win) {
    int bid = blockIdx.x;
    int tid = threadIdx.x;

    if (bid < 256) {
        const float* src = (bid < 128) ? Wrec : Win;
        uint32_t*    dst = (bid < 128) ? g_wrec : g_win;
        int i = (bid & 127) * 384 + tid;    // 0..49151
        int n = i >> 7, k = i & 127;
        dst[n * 128 + quad_off(n, k)] = f2tf32(src[k * G3 + n]);
    } else if (bid < 299) {
        int i = (bid - 256) * 384 + tid;
        if (i < D_ * D_) {
            int dp = i >> 7, d = i & 127;
            float acc = 0.f;
            #pragma unroll 4
            for (int e = 0; e < D_; e++) acc += wk[d * D_ + e] * wq[dp * D_ + e];
            g_wkqT[dp * D_ + d] = acc;
        }
    } else {
        // zero-input row of g_proj (interleaved); bz,br folded, bh separate
        int e = tid & 127, g = tid >> 7;   // g in 0..2
        float v = bin[g * 128 + e];
        if (g < 2) v += brec[g * 128 + e];
        g_proj[(size_t)B_ * E_ * PROJ_STRIDE + e * 4 + g] = v;
    }
}

// ---------------- proj via tf32 mma ------------------------------------------
// 64 rows/CTA, 512 threads (16 warps). Warp w owns e-cols [8w,8w+8) of all 3 gates.
#define PROJ_SMEM ((G3 * D_ + 64 * D_) * 4)   // 229376
__global__ void __launch_bounds__(512, 1)
k_proj_mma(const float* __restrict__ inp, const float* __restrict__ bin,
           const float* __restrict__ brec) {
    extern __shared__ float sm[];
    uint32_t* Wb = (uint32_t*)sm;         // 49152 words
    uint32_t* Ab = Wb + G3 * D_;          // 64*128 words

    int tid  = threadIdx.x;
    int w    = tid >> 5, lane = tid & 31;
    int gid  = lane >> 2, tig = lane & 3;
    int xorb = gid & 3;
    int row0 = blockIdx.x * 64;

    {   // stage W image + input rows (tf32, quad-fragment layout)
        const float4* s = (const float4*)g_win;
        float4*       d = (float4*)Wb;
        #pragma unroll 4
        for (int i = tid; i < G3 * D_ / 4; i += 512) d[i] = s[i];
        const float* ip = inp + (size_t)row0 * DIN_;
        for (int i = tid; i < 64 * DIN_; i += 512) {
            int r = i >> 7, k = i & 127;
            Ab[r * 128 + quad_off(r, k)] = f2tf32(ip[i]);
        }
    }
    __syncthreads();

    const int ecol = 8 * w + 2 * tig;
    float2 bias[3];
    #pragma unroll
    for (int g = 0; g < 3; g++) {
        int n = g * 128 + ecol;
        bias[g] = *(const float2*)(bin + n);
        if (g < 2) {
            float2 bb2 = *(const float2*)(brec + n);
            bias[g].x += bb2.x; bias[g].y += bb2.y;
        }
    }

    float acc[4][3][4];
    #pragma unroll
    for (int a = 0; a < 4; a++)
        for (int q = 0; q < 3; q++)
            for (int c = 0; c < 4; c++) acc[a][q][c] = 0.f;

    #pragma unroll
    for (int kg = 0; kg < 8; kg++) {
        int koff = 16 * (kg ^ xorb) + 4 * tig;
        uint4 bf[3];
        #pragma unroll
        for (int g = 0; g < 3; g++)
            bf[g] = *(const uint4*)(Wb + (g * 128 + 8 * w + gid) * 128 + koff);
        #pragma unroll
        for (int mt = 0; mt < 4; mt++) {
            int r = 16 * mt + gid;
            uint4 alo = *(const uint4*)(Ab + r * 128 + koff);
            uint4 ahi = *(const uint4*)(Ab + (r + 8) * 128 + koff);
            #pragma unroll
            for (int g = 0; g < 3; g++) {
                mma8(acc[mt][g], alo.x, ahi.x, alo.y, ahi.y, bf[g].x, bf[g].y);
                mma8(acc[mt][g], alo.z, ahi.z, alo.w, ahi.w, bf[g].z, bf[g].w);
            }
        }
    }

    #pragma unroll
    for (int mt = 0; mt < 4; mt++)
        #pragma unroll
        for (int hf = 0; hf < 2; hf++) {
            int r = 16 * mt + 8 * hf + gid;
            float* grow = g_proj + (size_t)(row0 + r) * PROJ_STRIDE;
            *(float4*)(grow + ecol * 4) =
                make_float4(acc[mt][0][hf * 2] + bias[0].x,
                            acc[mt][1][hf * 2] + bias[1].x,
                            acc[mt][2][hf * 2] + bias[2].x, 0.f);
            *(float4*)(grow + ecol * 4 + 4) =
                make_float4(acc[mt][0][hf * 2 + 1] + bias[0].y,
                            acc[mt][1][hf * 2 + 1] + bias[1].y,
                            acc[mt][2][hf * 2 + 1] + bias[2].y, 0.f);
        }
}

// ---------------- fused GRU: 2 interleaved 32-row tiles, 8 warps --------------
// 64 rows/CTA (grid 512), 256 threads. Warp w owns e-cols [16w,16w+16) (2 n-tiles)
// x 3 gates for BOTH tiles. B fragments loaded once per kg serve both tiles'
// independent mma chains (2x ILP). Single-buffered h per tile, 2 barriers/step.
#define GRU_ROWS 64
#define TILE_R   32
#define GRU_SMEM (G3 * D_ * 4 + 2 * TILE_R * D_ * 4 + GRU_ROWS * LMAX * 2)  // 231424
__global__ void __launch_bounds__(256, 1)
k_gru_fused(const float* __restrict__ brec, const float* __restrict__ wv,
            float* __restrict__ out) {
    extern __shared__ float sm[];
    uint32_t*  Wb   = (uint32_t*)sm;                  // 49152 words
    uint32_t*  hbA  = Wb + G3 * D_;                   // 32*128 words (tile A h, tf32)
    uint32_t*  hbB  = hbA + TILE_R * D_;              // 32*128 words (tile B h)
    uint16_t*  prow = (uint16_t*)(hbB + TILE_R * D_); // 64*16 u16

    int tid  = threadIdx.x;
    int w    = tid >> 5, lane = tid & 31;
    int gid  = lane >> 2, tig = lane & 3;
    int xorb = gid & 3;
    int n0   = blockIdx.x * GRU_ROWS;
    int bb   = n0 >> 11;                // batch index (64 | 2048)
    int p0   = n0 & (P_ - 1);

    {   // stage W image + gather row ids (u16; 16384 = zero row)
        const float4* s = (const float4*)g_wrec;
        float4*       d = (float4*)Wb;
        #pragma unroll 8
        for (int i = tid; i < G3 * D_ / 4; i += 256) d[i] = s[i];
        for (int i = tid; i < GRU_ROWS * LMAX; i += 256) {
            int e1 = g_lut[p0 * LMAX + i];
            prow[i] = (uint16_t)(e1 > 0 ? (bb * E_ + e1 - 1) : B_ * E_);
        }
    }
    __syncthreads();

    // thread's e columns: ec(nt) = 16w + 8nt + 2tig
    const int ec0 = 16 * w + 2 * tig;
    const int ec1 = ec0 + 8;
    float bh_[2][2];
    bh_[0][0] = brec[256 + ec0];  bh_[0][1] = brec[256 + ec0 + 1];
    bh_[1][0] = brec[256 + ec1];  bh_[1][1] = brec[256 + ec1 + 1];

    float holdA[4][2][2], holdB[4][2][2];   // [grp=(mt,hf)][nt][p]
    #pragma unroll
    for (int a = 0; a < 4; a++)
        for (int c = 0; c < 2; c++)
            for (int d = 0; d < 2; d++) { holdA[a][c][d] = 0.f; holdB[a][c][d] = 0.f; }

    // h write word offsets in quad layout (rows written have r&3 == gid&3)
    const int wsw[2][2] = {
        { quad_off(gid, ec0), quad_off(gid, ec0 + 1) },
        { quad_off(gid, ec1), quad_off(gid, ec1 + 1) }
    };

    for (int t = 0; t < LMAX; t++) {
        // ---- mma for BOTH tiles, shared B fragment loads ----
        float accA[2][6][4], accB[2][6][4];   // [mt][g*2+nt][..]
        #pragma unroll
        for (int a = 0; a < 2; a++)
            for (int q = 0; q < 6; q++)
                for (int c = 0; c < 4; c++) { accA[a][q][c] = 0.f; accB[a][q][c] = 0.f; }

        if (t > 0) {   // h==0 at t=0
            #pragma unroll
            for (int kg = 0; kg < 8; kg++) {
                int koff = 16 * (kg ^ xorb) + 4 * tig;
                uint4 bf[6];
                #pragma unroll
                for (int g = 0; g < 3; g++)
                    #pragma unroll
                    for (int nt = 0; nt < 2; nt++)
                        bf[g * 2 + nt] = *(const uint4*)(Wb + (g * 128 + 16 * w + 8 * nt + gid) * 128 + koff);
                #pragma unroll
                for (int mt = 0; mt < 2; mt++) {
                    int r = 16 * mt + gid;
                    uint4 aloA = *(const uint4*)(hbA + r * 128 + koff);
                    uint4 ahiA = *(const uint4*)(hbA + (r + 8) * 128 + koff);
                    uint4 aloB = *(const uint4*)(hbB + r * 128 + koff);
                    uint4 ahiB = *(const uint4*)(hbB + (r + 8) * 128 + koff);
                    #pragma unroll
                    for (int q = 0; q < 6; q++) {
                        mma8(accA[mt][q], aloA.x, ahiA.x, aloA.y, ahiA.y, bf[q].x, bf[q].y);
                        mma8(accA[mt][q], aloA.z, ahiA.z, aloA.w, ahiA.w, bf[q].z, bf[q].w);
                        mma8(accB[mt][q], aloB.x, ahiB.x, aloB.y, ahiB.y, bf[q].x, bf[q].y);
                        mma8(accB[mt][q], aloB.z, ahiB.z, aloB.w, ahiB.w, bf[q].z, bf[q].w);
                    }
                }
            }
        }

        // prefetch first gather group of each tile (independent of h)
        float4 xgA[2][4], xgB[2][4];   // ping-pong [buf][nt*2+p]
        {
            int rA = gid;                             // grp0: mt=0,hf=0
            const float4* xpA = (const float4*)(g_proj + (size_t)prow[rA * LMAX + t] * PROJ_STRIDE);
            xgA[0][0] = xpA[ec0]; xgA[0][1] = xpA[ec0 + 1];
            xgA[0][2] = xpA[ec1]; xgA[0][3] = xpA[ec1 + 1];
            const float4* xpB = (const float4*)(g_proj + (size_t)prow[(TILE_R + rA) * LMAX + t] * PROJ_STRIDE);
            xgB[0][0] = xpB[ec0]; xgB[0][1] = xpB[ec0 + 1];
            xgB[0][2] = xpB[ec1]; xgB[0][3] = xpB[ec1 + 1];
        }
        __syncthreads();   // all mma reads of hbA/hbB complete

        // ---- elementwise updates, pipelined gathers. grp=(mt=grp>>1, hf=grp&1) ----
        #pragma unroll
        for (int grp = 0; grp < 4; grp++) {
            int r = 16 * (grp >> 1) + 8 * (grp & 1) + gid;
            if (grp < 3) {   // prefetch next group, tile A
                int rn = 16 * ((grp + 1) >> 1) + 8 * ((grp + 1) & 1) + gid;
                const float4* xp = (const float4*)(g_proj + (size_t)prow[rn * LMAX + t] * PROJ_STRIDE);
                xgA[(grp + 1) & 1][0] = xp[ec0]; xgA[(grp + 1) & 1][1] = xp[ec0 + 1];
                xgA[(grp + 1) & 1][2] = xp[ec1]; xgA[(grp + 1) & 1][3] = xp[ec1 + 1];
            }
            float4* xc = xgA[grp & 1];
            int mt = grp >> 1, hf = grp & 1;
            #pragma unroll
            for (int nt = 0; nt < 2; nt++) {
                float hn[2];
                #pragma unroll
                for (int p = 0; p < 2; p++) {
                    float4 xv = xc[nt * 2 + p];
                    float z  = sigf(xv.x + accA[mt][0 + nt][hf * 2 + p]);
                    float rr = sigf(xv.y + accA[mt][2 + nt][hf * 2 + p]);
                    float hc = tanha(xv.z + rr * (accA[mt][4 + nt][hf * 2 + p] + bh_[nt][p]));
                    float hv = z * holdA[grp][nt][p] + (1.0f - z) * hc;
                    holdA[grp][nt][p] = hv;
                    hn[p] = hv;
                }
                if (t < LMAX - 1) {
                    hbA[r * 128 + wsw[nt][0]] = f2tf32(hn[0]);
                    hbA[r * 128 + wsw[nt][1]] = f2tf32(hn[1]);
                }
                *(float2*)(g_hs + (size_t)(n0 + r) * (LMAX * D_) + t * D_
                           + (nt ? ec1 : ec0)) = make_float2(hn[0], hn[1]);
            }
        }
        #pragma unroll
        for (int grp = 0; grp < 4; grp++) {
            int r = 16 * (grp >> 1) + 8 * (grp & 1) + gid;
            if (grp < 3) {   // prefetch next group, tile B
                int rn = 16 * ((grp + 1) >> 1) + 8 * ((grp + 1) & 1) + gid;
                const float4* xp = (const float4*)(g_proj + (size_t)prow[(TILE_R + rn) * LMAX + t] * PROJ_STRIDE);
                xgB[(grp + 1) & 1][0] = xp[ec0]; xgB[(grp + 1) & 1][1] = xp[ec0 + 1];
                xgB[(grp + 1) & 1][2] = xp[ec1]; xgB[(grp + 1) & 1][3] = xp[ec1 + 1];
            }
            float4* xc = xgB[grp & 1];
            int mt = grp >> 1, hf = grp & 1;
            #pragma unroll
            for (int nt = 0; nt < 2; nt++) {
                float hn[2];
                #pragma unroll
                for (int p = 0; p < 2; p++) {
                    float4 xv = xc[nt * 2 + p];
                    float z  = sigf(xv.x + accB[mt][0 + nt][hf * 2 + p]);
                    float rr = sigf(xv.y + accB[mt][2 + nt][hf * 2 + p]);
                    float hc = tanha(xv.z + rr * (accB[mt][4 + nt][hf * 2 + p] + bh_[nt][p]));
                    float hv = z * holdB[grp][nt][p] + (1.0f - z) * hc;
                    holdB[grp][nt][p] = hv;
                    hn[p] = hv;
                }
                if (t < LMAX - 1) {
                    hbB[r * 128 + wsw[nt][0]] = f2tf32(hn[0]);
                    hbB[r * 128 + wsw[nt][1]] = f2tf32(hn[1]);
                }
                *(float2*)(g_hs + (size_t)(n0 + TILE_R + r) * (LMAX * D_) + t * D_
                           + (nt ? ec1 : ec0)) = make_float2(hn[0], hn[1]);
            }
        }
        __syncthreads();   // h writes visible before next step's mma
    }

    // ============ fused attention epilogue (shfl4, 8 rows/warp) ============
    float* wkqS = sm;           // 16384 words
    float* wvS  = sm + 16384;   // 16384 words
    {
        const float4* s4 = (const float4*)g_wkqT;
        const float4* t4 = (const float4*)wv;
        float4*       a4 = (float4*)wkqS;
        float4*       b4 = (float4*)wvS;
        for (int i = tid; i < 4096; i += 256) { a4[i] = s4[i]; b4[i] = t4[i]; }
    }
    __syncthreads();

    const float4* wkq4 = (const float4*)wkqS;
    const float4* wv4  = (const float4*)wvS;

    #pragma unroll 1
    for (int rr = 0; rr < 8; rr++) {
        int row = n0 + 8 * w + rr;
        float4 hrow[LMAX];
        const float4* g4 = (const float4*)(g_hs + (size_t)row * (LMAX * D_));
        #pragma unroll
        for (int l = 0; l < LMAX; l++) hrow[l] = g4[l * 32 + lane];

        float4 last = hrow[LMAX - 1];
        float4 m = make_float4(0.f, 0.f, 0.f, 0.f);
        #pragma unroll 4
        for (int dg = 0; dg < 32; dg++) {
            float4 lv = shfl4(last, dg);
            m.x = fmaf(lv.x, wkq4[(4 * dg + 0) * 32 + lane].x, m.x);
            m.y = fmaf(lv.x, wkq4[(4 * dg + 0) * 32 + lane].y, m.y);
            m.z = fmaf(lv.x, wkq4[(4 * dg + 0) * 32 + lane].z, m.z);
            m.w = fmaf(lv.x, wkq4[(4 * dg + 0) * 32 + lane].w, m.w);
            m.x = fmaf(lv.y, wkq4[(4 * dg + 1) * 32 + lane].x, m.x);
            m.y = fmaf(lv.y, wkq4[(4 * dg + 1) * 32 + lane].y, m.y);
            m.z = fmaf(lv.y, wkq4[(4 * dg + 1) * 32 + lane].z, m.z);
            m.w = fmaf(lv.y, wkq4[(4 * dg + 1) * 32 + lane].w, m.w);
            m.x = fmaf(lv.z, wkq4[(4 * dg + 2) * 32 + lane].x, m.x);
            m.y = fmaf(lv.z, wkq4[(4 * dg + 2) * 32 + lane].y, m.y);
            m.z = fmaf(lv.z, wkq4[(4 * dg + 2) * 32 + lane].z, m.z);
            m.w = fmaf(lv.z, wkq4[(4 * dg + 2) * 32 + lane].w, m.w);
            m.x = fmaf(lv.w, wkq4[(4 * dg + 3) * 32 + lane].x, m.x);
            m.y = fmaf(lv.w, wkq4[(4 * dg + 3) * 32 + lane].y, m.y);
            m.z = fmaf(lv.w, wkq4[(4 * dg + 3) * 32 + lane].z, m.z);
            m.w = fmaf(lv.w, wkq4[(4 * dg + 3) * 32 + lane].w, m.w);
        }

        float4 u = make_float4(0.f, 0.f, 0.f, 0.f);
        #pragma unroll
        for (int l = 0; l < LMAX; l++) {
            float4 h4 = hrow[l];
            float  pp = m.x * h4.x + m.y * h4.y + m.z * h4.z + m.w * h4.w;
            #pragma unroll
            for (int o = 16; o > 0; o >>= 1) pp += __shfl_xor_sync(0xffffffffu, pp, o);
            u.x = fmaf(pp, h4.x, u.x); u.y = fmaf(pp, h4.y, u.y);
            u.z = fmaf(pp, h4.z, u.z); u.w = fmaf(pp, h4.w, u.w);
        }

        float4 c = make_float4(0.f, 0.f, 0.f, 0.f);
        #pragma unroll 4
        for (int dg = 0; dg < 32; dg++) {
            float4 uv = shfl4(u, dg);
            c.x = fmaf(uv.x, wv4[(4 * dg + 0) * 32 + lane].x, c.x);
            c.y = fmaf(uv.x, wv4[(4 * dg + 0) * 32 + lane].y, c.y);
            c.z = fmaf(uv.x, wv4[(4 * dg + 0) * 32 + lane].z, c.z);
            c.w = fmaf(uv.x, wv4[(4 * dg + 0) * 32 + lane].w, c.w);
            c.x = fmaf(uv.y, wv4[(4 * dg + 1) * 32 + lane].x, c.x);
            c.y = fmaf(uv.y, wv4[(4 * dg + 1) * 32 + lane].y, c.y);
            c.z = fmaf(uv.y, wv4[(4 * dg + 1) * 32 + lane].z, c.z);
            c.w = fmaf(uv.y, wv4[(4 * dg + 1) * 32 + lane].w, c.w);
            c.x = fmaf(uv.z, wv4[(4 * dg + 2) * 32 + lane].x, c.x);
            c.y = fmaf(uv.z, wv4[(4 * dg + 2) * 32 + lane].y, c.y);
            c.z = fmaf(uv.z, wv4[(4 * dg + 2) * 32 + lane].z, c.z);
            c.w = fmaf(uv.z, wv4[(4 * dg + 2) * 32 + lane].w, c.w);
            c.x = fmaf(uv.w, wv4[(4 * dg + 3) * 32 + lane].x, c.x);
            c.y = fmaf(uv.w, wv4[(4 * dg + 3) * 32 + lane].y, c.y);
            c.z = fmaf(uv.w, wv4[(4 * dg + 3) * 32 + lane].z, c.z);
            c.w = fmaf(uv.w, wv4[(4 * dg + 3) * 32 + lane].w, c.w);
        }
        *(float4*)&out[(size_t)row * 128 + 4 * lane] = c;
    }
}

// ---------------- launch -----------------------------------------------------
extern "C" void kernel_launch(void* const* d_in, const int* in_sizes, int n_in,
                              void* d_out, int out_size) {
    const float* inputs = (const float*)d_in[0];
    const float* W_in   = (const float*)d_in[1];
    const float* W_rec  = (const float*)d_in[2];
    const float* b_in   = (const float*)d_in[3];
    const float* b_rec  = (const float*)d_in[4];
    const float* wq     = (const float*)d_in[5];
    const float* wk     = (const float*)d_in[6];
    const float* wv     = (const float*)d_in[7];
    const int*   paths  = (const int*)d_in[8];
    const int*   idx    = (const int*)d_in[9];
    const int*   seqs   = (const int*)d_in[10];
    int T = in_sizes[8];

    cudaFuncSetAttribute(k_proj_mma,  cudaFuncAttributeMaxDynamicSharedMemorySize, PROJ_SMEM);
    cudaFuncSetAttribute(k_gru_fused, cudaFuncAttributeMaxDynamicSharedMemorySize, GRU_SMEM);

    // fused GRU+attn is launch #4 (the one ncu samples)
    k_lut_fill<<<(T + 255) / 256, 256>>>(paths, idx, seqs, T);
    k_prep<<<300, 384>>>(b_in, b_rec, wk, wq, W_rec, W_in);
    k_proj_mma<<<(B_ * E_) / 64, 512, PROJ_SMEM>>>(inputs, b_in, b_rec);
    k_gru_fused<<<(B_ * P_) / GRU_ROWS, 256, GRU_SMEM>>>(b_rec, wv, (float*)d_out);
}

// round 13
// speedup vs baseline: 1.1342x; 1.1342x over previous
#include <cuda_runtime.h>
#include <math.h>
#include <stdint.h>

// Problem constants (fixed by the reference)
#define B_   16
#define E_   1024
#define DIN_ 128
#define P_   2048
#define D_   128
#define LMAX 16
#define G3   384   // 3*D
#define PROJ_STRIDE 512   // gate-interleaved proj row: [e*4 + {z,r,h,pad}]

// ---------------- scratch (device globals: no allocations allowed) ---------
__device__ int      g_lut[P_ * LMAX];                          // path+1 per (p,t), 0 if empty (BSS zero)
__device__ float    g_proj[((size_t)B_ * E_ + 1) * PROJ_STRIDE];  // interleaved proj; row 16384 = zero row
__device__ float    g_wkqT[D_ * D_];                           // g_wkqT[dp*128+d] = (WkWq^T)[d][dp]
__device__ float    g_hs[(size_t)B_ * P_ * LMAX * D_];         // GRU hidden states (fp32)
__device__ uint32_t g_wrec[G3 * D_];                           // W_rec^T tf32 quad-fragment image
__device__ uint32_t g_win[G3 * D_];                            // W_in^T  tf32 quad-fragment image

__device__ __forceinline__ float tanha(float x) {
    float r; asm("tanh.approx.f32 %0, %1;" : "=f"(r) : "f"(x)); return r;
}
__device__ __forceinline__ float sigf(float x) { return fmaf(tanha(0.5f * x), 0.5f, 0.5f); }

__device__ __forceinline__ uint32_t f2tf32(float v) {
    uint32_t r;
    asm("cvt.rna.tf32.f32 %0, %1;" : "=r"(r) : "f"(v));
    return r;
}

// quad-fragment word offset within a 128-word row image:
//   off(n,k) = 16*((k>>4)^(n&3)) + 4*(k&3) + 2*((k>>3)&1) + ((k>>2)&1)
__device__ __forceinline__ int quad_off(int n, int k) {
    return 16 * (((k >> 4)) ^ (n & 3)) + 4 * (k & 3) + 2 * ((k >> 3) & 1) + ((k >> 2) & 1);
}

// mma.sync m16n8k8 tf32: D += A*B (fp32 accum)
__device__ __forceinline__ void mma8(float* c, uint32_t a0, uint32_t a1, uint32_t a2, uint32_t a3,
                                     uint32_t b0, uint32_t b1) {
    asm volatile("mma.sync.aligned.m16n8k8.row.col.f32.tf32.tf32.f32 "
                 "{%0,%1,%2,%3}, {%4,%5,%6,%7}, {%8,%9}, {%0,%1,%2,%3};"
                 : "+f"(c[0]), "+f"(c[1]), "+f"(c[2]), "+f"(c[3])
                 : "r"(a0), "r"(a1), "r"(a2), "r"(a3), "r"(b0), "r"(b1));
}

__device__ __forceinline__ float4 shfl4(float4 v, int src) {
    float4 r;
    r.x = __shfl_sync(0xffffffffu, v.x, src);
    r.y = __shfl_sync(0xffffffffu, v.y, src);
    r.z = __shfl_sync(0xffffffffu, v.z, src);
    r.w = __shfl_sync(0xffffffffu, v.w, src);
    return r;
}

// ---------------- merged setup kernel ----------------------------------------
// blocks [0,128)=W_rec image, [128,256)=W_in image, [256,299)=wkq, 299=bias0,
// [300, 300+lut_blocks)=lut fill. All parts independent.
__global__ void __launch_bounds__(384, 2)
k_setup(const float* __restrict__ bin, const float* __restrict__ brec,
        const float* __restrict__ wk,  const float* __restrict__ wq,
        const float* __restrict__ Wrec, const float* __restrict__ Win,
        const int* __restrict__ paths, const int* __restrict__ idx,
        const int* __restrict__ seqs, int T) {
    int bid = blockIdx.x;
    int tid = threadIdx.x;

    if (bid < 256) {
        const float* src = (bid < 128) ? Wrec : Win;
        uint32_t*    dst = (bid < 128) ? g_wrec : g_win;
        int i = (bid & 127) * 384 + tid;    // 0..49151
        int n = i >> 7, k = i & 127;
        dst[n * 128 + quad_off(n, k)] = f2tf32(src[k * G3 + n]);
    } else if (bid < 299) {
        int i = (bid - 256) * 384 + tid;
        if (i < D_ * D_) {
            int dp = i >> 7, d = i & 127;
            float acc = 0.f;
            #pragma unroll 4
            for (int e = 0; e < D_; e++) acc += wk[d * D_ + e] * wq[dp * D_ + e];
            g_wkqT[dp * D_ + d] = acc;
        }
    } else if (bid == 299) {
        // zero-input row of g_proj (interleaved); bz,br folded, bh separate
        int e = tid & 127, g = tid >> 7;   // g in 0..2
        float v = bin[g * 128 + e];
        if (g < 2) v += brec[g * 128 + e];
        g_proj[(size_t)B_ * E_ * PROJ_STRIDE + e * 4 + g] = v;
    } else {
        int j = (bid - 300) * 384 + tid;
        if (j < T) g_lut[idx[j] * LMAX + seqs[j]] = paths[j] + 1;
    }
}

// ---------------- proj via tf32 mma ------------------------------------------
// 64 rows/CTA, 512 threads (16 warps). Warp w owns e-cols [8w,8w+8) of all 3 gates.
#define PROJ_SMEM ((G3 * D_ + 64 * D_) * 4)   // 229376
__global__ void __launch_bounds__(512, 1)
k_proj_mma(const float* __restrict__ inp, const float* __restrict__ bin,
           const float* __restrict__ brec) {
    extern __shared__ float sm[];
    uint32_t* Wb = (uint32_t*)sm;         // 49152 words
    uint32_t* Ab = Wb + G3 * D_;          // 64*128 words

    int tid  = threadIdx.x;
    int w    = tid >> 5, lane = tid & 31;
    int gid  = lane >> 2, tig = lane & 3;
    int xorb = gid & 3;
    int row0 = blockIdx.x * 64;

    {   // stage W image + input rows (tf32, quad-fragment layout)
        const float4* s = (const float4*)g_win;
        float4*       d = (float4*)Wb;
        #pragma unroll 4
        for (int i = tid; i < G3 * D_ / 4; i += 512) d[i] = s[i];
        const float* ip = inp + (size_t)row0 * DIN_;
        for (int i = tid; i < 64 * DIN_; i += 512) {
            int r = i >> 7, k = i & 127;
            Ab[r * 128 + quad_off(r, k)] = f2tf32(ip[i]);
        }
    }
    __syncthreads();

    const int ecol = 8 * w + 2 * tig;
    float2 bias[3];
    #pragma unroll
    for (int g = 0; g < 3; g++) {
        int n = g * 128 + ecol;
        bias[g] = *(const float2*)(bin + n);
        if (g < 2) {
            float2 bb2 = *(const float2*)(brec + n);
            bias[g].x += bb2.x; bias[g].y += bb2.y;
        }
    }

    float acc[4][3][4];
    #pragma unroll
    for (int a = 0; a < 4; a++)
        for (int q = 0; q < 3; q++)
            for (int c = 0; c < 4; c++) acc[a][q][c] = 0.f;

    #pragma unroll
    for (int kg = 0; kg < 8; kg++) {
        int koff = 16 * (kg ^ xorb) + 4 * tig;
        uint4 bf[3];
        #pragma unroll
        for (int g = 0; g < 3; g++)
            bf[g] = *(const uint4*)(Wb + (g * 128 + 8 * w + gid) * 128 + koff);
        #pragma unroll
        for (int mt = 0; mt < 4; mt++) {
            int r = 16 * mt + gid;
            uint4 alo = *(const uint4*)(Ab + r * 128 + koff);
            uint4 ahi = *(const uint4*)(Ab + (r + 8) * 128 + koff);
            #pragma unroll
            for (int g = 0; g < 3; g++) {
                mma8(acc[mt][g], alo.x, ahi.x, alo.y, ahi.y, bf[g].x, bf[g].y);
                mma8(acc[mt][g], alo.z, ahi.z, alo.w, ahi.w, bf[g].z, bf[g].w);
            }
        }
    }

    #pragma unroll
    for (int mt = 0; mt < 4; mt++)
        #pragma unroll
        for (int hf = 0; hf < 2; hf++) {
            int r = 16 * mt + 8 * hf + gid;
            float* grow = g_proj + (size_t)(row0 + r) * PROJ_STRIDE;
            *(float4*)(grow + ecol * 4) =
                make_float4(acc[mt][0][hf * 2] + bias[0].x,
                            acc[mt][1][hf * 2] + bias[1].x,
                            acc[mt][2][hf * 2] + bias[2].x, 0.f);
            *(float4*)(grow + ecol * 4 + 4) =
                make_float4(acc[mt][0][hf * 2 + 1] + bias[0].y,
                            acc[mt][1][hf * 2 + 1] + bias[1].y,
                            acc[mt][2][hf * 2 + 1] + bias[2].y, 0.f);
        }
}

// ---------------- fused tf32-HMMA GRU + shfl4 attention (R9 config) -----------
// 32 rows/CTA (grid 1024), 512 threads (16 warps). Warp w owns e-cols [8w,8w+8)
// of all 3 gates; 2 m-tiles. Double-buffered tf32 h, 1 barrier/step.
#define GRU_ROWS 32
#define GRU_SMEM (G3 * D_ * 4 + 2 * GRU_ROWS * D_ * 4 + GRU_ROWS * LMAX * 2)  // 230400
__global__ void __launch_bounds__(512, 1)
k_gru_fused(const float* __restrict__ brec, const float* __restrict__ wv,
            float* __restrict__ out) {
    extern __shared__ float sm[];
    uint32_t*  Wb   = (uint32_t*)sm;                  // 49152 words
    uint32_t*  hb0  = Wb + G3 * D_;                   // 32*128 words (tf32 bits of h)
    uint32_t*  hb1  = hb0 + GRU_ROWS * D_;            // 32*128 words
    uint16_t*  prow = (uint16_t*)(hb1 + GRU_ROWS * D_);  // 32*16 u16

    int tid  = threadIdx.x;
    int w    = tid >> 5, lane = tid & 31;
    int gid  = lane >> 2, tig = lane & 3;
    int xorb = gid & 3;
    int n0   = blockIdx.x * GRU_ROWS;
    int bb   = n0 >> 11;                // batch index (32 | 2048)
    int p0   = n0 & (P_ - 1);

    {   // stage W image + gather row ids (u16; 16384 = zero row)
        const float4* s = (const float4*)g_wrec;
        float4*       d = (float4*)Wb;
        #pragma unroll 4
        for (int i = tid; i < G3 * D_ / 4; i += 512) d[i] = s[i];
        if (tid < GRU_ROWS * LMAX) {
            int e1 = g_lut[p0 * LMAX + tid];
            prow[tid] = (uint16_t)(e1 > 0 ? (bb * E_ + e1 - 1) : B_ * E_);
        }
    }
    __syncthreads();

    const int ecol = 8 * w + 2 * tig;
    float bh0 = brec[256 + ecol];
    float bh1 = brec[256 + ecol + 1];

    float hold[2][2][2];   // [mt][hf][p]
    #pragma unroll
    for (int a = 0; a < 2; a++)
        for (int b = 0; b < 2; b++)
            for (int c = 0; c < 2; c++) hold[a][b][c] = 0.f;

    // h write word offsets (cols ecol, ecol+1) in quad layout
    const int wsw0 = quad_off(gid, ecol);
    const int wsw1 = quad_off(gid, ecol + 1);

    for (int t = 0; t < LMAX; t++) {
        uint32_t* hcur = (t & 1) ? hb1 : hb0;
        uint32_t* hnxt = (t & 1) ? hb0 : hb1;

        // ---- prefetch x-gates (interleaved proj: one float4 per column) ----
        float4 xq[2][2][2];   // [mt][hf][col p]
        #pragma unroll
        for (int mt = 0; mt < 2; mt++)
            #pragma unroll
            for (int hf = 0; hf < 2; hf++) {
                int r = 16 * mt + 8 * hf + gid;
                const float4* xp = (const float4*)(g_proj + (size_t)prow[r * LMAX + t] * PROJ_STRIDE);
                xq[mt][hf][0] = xp[ecol];
                xq[mt][hf][1] = xp[ecol + 1];
            }

        // ---- gates = h @ W_rec  (tf32 mma, quad LDS.128 fragments) ----
        float acc[2][3][4];
        #pragma unroll
        for (int a = 0; a < 2; a++)
            for (int q = 0; q < 3; q++)
                for (int c = 0; c < 4; c++) acc[a][q][c] = 0.f;

        if (t > 0) {   // h==0 at t=0
            #pragma unroll
            for (int kg = 0; kg < 8; kg++) {
                int koff = 16 * (kg ^ xorb) + 4 * tig;
                uint4 bf[3];
                #pragma unroll
                for (int g = 0; g < 3; g++)
                    bf[g] = *(const uint4*)(Wb + (g * 128 + 8 * w + gid) * 128 + koff);
                #pragma unroll
                for (int mt = 0; mt < 2; mt++) {
                    int r = 16 * mt + gid;
                    uint4 alo = *(const uint4*)(hcur + r * 128 + koff);
                    uint4 ahi = *(const uint4*)(hcur + (r + 8) * 128 + koff);
                    #pragma unroll
                    for (int g = 0; g < 3; g++) {
                        mma8(acc[mt][g], alo.x, ahi.x, alo.y, ahi.y, bf[g].x, bf[g].y);
                        mma8(acc[mt][g], alo.z, ahi.z, alo.w, ahi.w, bf[g].z, bf[g].w);
                    }
                }
            }
        }

        // ---- elementwise GRU update (writes the OTHER buffer) ----
        #pragma unroll
        for (int mt = 0; mt < 2; mt++)
            #pragma unroll
            for (int hf = 0; hf < 2; hf++) {
                int r = 16 * mt + 8 * hf + gid;
                float hn[2];
                #pragma unroll
                for (int p = 0; p < 2; p++) {
                    float4 xc = xq[mt][hf][p];
                    float bhv = p ? bh1 : bh0;
                    float z  = sigf(xc.x + acc[mt][0][hf * 2 + p]);
                    float rr = sigf(xc.y + acc[mt][1][hf * 2 + p]);
                    float hc = tanha(xc.z + rr * (acc[mt][2][hf * 2 + p] + bhv));
                    float hv = z * hold[mt][hf][p] + (1.0f - z) * hc;
                    hold[mt][hf][p] = hv;
                    hn[p] = hv;
                }
                if (t < LMAX - 1) {
                    hnxt[r * 128 + wsw0] = f2tf32(hn[0]);
                    hnxt[r * 128 + wsw1] = f2tf32(hn[1]);
                }
                *(float2*)(g_hs + (size_t)(n0 + r) * (LMAX * D_) + t * D_ + ecol)
                    = make_float2(hn[0], hn[1]);
            }
        __syncthreads();
    }

    // ============ fused attention epilogue (shfl4, 2 rows/warp) ============
    float* wkqS = sm;           // 16384 words
    float* wvS  = sm + 16384;   // 16384 words
    {
        const float4* s4 = (const float4*)g_wkqT;
        const float4* t4 = (const float4*)wv;
        float4*       a4 = (float4*)wkqS;
        float4*       b4 = (float4*)wvS;
        for (int i = tid; i < 4096; i += 512) { a4[i] = s4[i]; b4[i] = t4[i]; }
    }
    __syncthreads();

    const float4* wkq4 = (const float4*)wkqS;
    const float4* wv4  = (const float4*)wvS;

    #pragma unroll 1
    for (int rr = 0; rr < 2; rr++) {
        int row = n0 + 2 * w + rr;
        float4 hrow[LMAX];
        const float4* g4 = (const float4*)(g_hs + (size_t)row * (LMAX * D_));
        #pragma unroll
        for (int l = 0; l < LMAX; l++) hrow[l] = g4[l * 32 + lane];

        float4 last = hrow[LMAX - 1];
        float4 m = make_float4(0.f, 0.f, 0.f, 0.f);
        #pragma unroll 4
        for (int dg = 0; dg < 32; dg++) {
            float4 lv = shfl4(last, dg);
            m.x = fmaf(lv.x, wkq4[(4 * dg + 0) * 32 + lane].x, m.x);
            m.y = fmaf(lv.x, wkq4[(4 * dg + 0) * 32 + lane].y, m.y);
            m.z = fmaf(lv.x, wkq4[(4 * dg + 0) * 32 + lane].z, m.z);
            m.w = fmaf(lv.x, wkq4[(4 * dg + 0) * 32 + lane].w, m.w);
            m.x = fmaf(lv.y, wkq4[(4 * dg + 1) * 32 + lane].x, m.x);
            m.y = fmaf(lv.y, wkq4[(4 * dg + 1) * 32 + lane].y, m.y);
            m.z = fmaf(lv.y, wkq4[(4 * dg + 1) * 32 + lane].z, m.z);
            m.w = fmaf(lv.y, wkq4[(4 * dg + 1) * 32 + lane].w, m.w);
            m.x = fmaf(lv.z, wkq4[(4 * dg + 2) * 32 + lane].x, m.x);
            m.y = fmaf(lv.z, wkq4[(4 * dg + 2) * 32 + lane].y, m.y);
            m.z = fmaf(lv.z, wkq4[(4 * dg + 2) * 32 + lane].z, m.z);
            m.w = fmaf(lv.z, wkq4[(4 * dg + 2) * 32 + lane].w, m.w);
            m.x = fmaf(lv.w, wkq4[(4 * dg + 3) * 32 + lane].x, m.x);
            m.y = fmaf(lv.w, wkq4[(4 * dg + 3) * 32 + lane].y, m.y);
            m.z = fmaf(lv.w, wkq4[(4 * dg + 3) * 32 + lane].z, m.z);
            m.w = fmaf(lv.w, wkq4[(4 * dg + 3) * 32 + lane].w, m.w);
        }

        float4 u = make_float4(0.f, 0.f, 0.f, 0.f);
        #pragma unroll
        for (int l = 0; l < LMAX; l++) {
            float4 h4 = hrow[l];
            float  pp = m.x * h4.x + m.y * h4.y + m.z * h4.z + m.w * h4.w;
            #pragma unroll
            for (int o = 16; o > 0; o >>= 1) pp += __shfl_xor_sync(0xffffffffu, pp, o);
            u.x = fmaf(pp, h4.x, u.x); u.y = fmaf(pp, h4.y, u.y);
            u.z = fmaf(pp, h4.z, u.z); u.w = fmaf(pp, h4.w, u.w);
        }

        float4 c = make_float4(0.f, 0.f, 0.f, 0.f);
        #pragma unroll 4
        for (int dg = 0; dg < 32; dg++) {
            float4 uv = shfl4(u, dg);
            c.x = fmaf(uv.x, wv4[(4 * dg + 0) * 32 + lane].x, c.x);
            c.y = fmaf(uv.x, wv4[(4 * dg + 0) * 32 + lane].y, c.y);
            c.z = fmaf(uv.x, wv4[(4 * dg + 0) * 32 + lane].z, c.z);
            c.w = fmaf(uv.x, wv4[(4 * dg + 0) * 32 + lane].w, c.w);
            c.x = fmaf(uv.y, wv4[(4 * dg + 1) * 32 + lane].x, c.x);
            c.y = fmaf(uv.y, wv4[(4 * dg + 1) * 32 + lane].y, c.y);
            c.z = fmaf(uv.y, wv4[(4 * dg + 1) * 32 + lane].z, c.z);
            c.w = fmaf(uv.y, wv4[(4 * dg + 1) * 32 + lane].w, c.w);
            c.x = fmaf(uv.z, wv4[(4 * dg + 2) * 32 + lane].x, c.x);
            c.y = fmaf(uv.z, wv4[(4 * dg + 2) * 32 + lane].y, c.y);
            c.z = fmaf(uv.z, wv4[(4 * dg + 2) * 32 + lane].z, c.z);
            c.w = fmaf(uv.z, wv4[(4 * dg + 2) * 32 + lane].w, c.w);
            c.x = fmaf(uv.w, wv4[(4 * dg + 3) * 32 + lane].x, c.x);
            c.y = fmaf(uv.w, wv4[(4 * dg + 3) * 32 + lane].y, c.y);
            c.z = fmaf(uv.w, wv4[(4 * dg + 3) * 32 + lane].z, c.z);
            c.w = fmaf(uv.w, wv4[(4 * dg + 3) * 32 + lane].w, c.w);
        }
        *(float4*)&out[(size_t)row * 128 + 4 * lane] = c;
    }
}

// ---------------- launch -----------------------------------------------------
extern "C" void kernel_launch(void* const* d_in, const int* in_sizes, int n_in,
                              void* d_out, int out_size) {
    const float* inputs = (const float*)d_in[0];
    const float* W_in   = (const float*)d_in[1];
    const float* W_rec  = (const float*)d_in[2];
    const float* b_in   = (const float*)d_in[3];
    const float* b_rec  = (const float*)d_in[4];
    const float* wq     = (const float*)d_in[5];
    const float* wk     = (const float*)d_in[6];
    const float* wv     = (const float*)d_in[7];
    const int*   paths  = (const int*)d_in[8];
    const int*   idx    = (const int*)d_in[9];
    const int*   seqs   = (const int*)d_in[10];
    int T = in_sizes[8];

    cudaFuncSetAttribute(k_proj_mma,  cudaFuncAttributeMaxDynamicSharedMemorySize, PROJ_SMEM);
    cudaFuncSetAttribute(k_gru_fused, cudaFuncAttributeMaxDynamicSharedMemorySize, GRU_SMEM);

    int lut_blocks = (T + 383) / 384;
    k_setup<<<300 + lut_blocks, 384>>>(b_in, b_rec, wk, wq, W_rec, W_in,
                                       paths, idx, seqs, T);
    k_proj_mma<<<(B_ * E_) / 64, 512, PROJ_SMEM>>>(inputs, b_in, b_rec);
    k_gru_fused<<<(B_ * P_) / GRU_ROWS, 512, GRU_SMEM>>>(b_rec, wv, (float*)d_out);
}

// round 14
// speedup vs baseline: 1.1568x; 1.0199x over previous
#include <cuda_runtime.h>
#include <math.h>
#include <stdint.h>

// Problem constants (fixed by the reference)
#define B_   16
#define E_   1024
#define DIN_ 128
#define P_   2048
#define D_   128
#define LMAX 16
#define G3   384   // 3*D
#define PROJ_STRIDE 512   // gate-interleaved proj row: [e*4 + {z,r,h,pad}]

// ---------------- scratch (device globals: no allocations allowed) ---------
__device__ int      g_lut[P_ * LMAX];                          // path+1 per (p,t), 0 if empty (BSS zero)
__device__ float    g_proj[((size_t)B_ * E_ + 1) * PROJ_STRIDE];  // interleaved proj; row 16384 = zero row
__device__ float    g_wkqT[D_ * D_];                           // g_wkqT[dp*128+d] = (WkWq^T)[d][dp]
__device__ float    g_hs[(size_t)B_ * P_ * LMAX * D_];         // GRU hidden states (fp32)
__device__ uint32_t g_wrec[G3 * D_];                           // W_rec^T tf32 quad-fragment image
__device__ uint32_t g_win[G3 * D_];                            // W_in^T  tf32 quad-fragment image

__device__ __forceinline__ float tanha(float x) {
    float r; asm("tanh.approx.f32 %0, %1;" : "=f"(r) : "f"(x)); return r;
}
__device__ __forceinline__ float sigf(float x) { return fmaf(tanha(0.5f * x), 0.5f, 0.5f); }

__device__ __forceinline__ uint32_t f2tf32(float v) {
    uint32_t r;
    asm("cvt.rna.tf32.f32 %0, %1;" : "=r"(r) : "f"(v));
    return r;
}

// quad-fragment word offset within a 128-word row image:
//   off(n,k) = 16*((k>>4)^(n&3)) + 4*(k&3) + 2*((k>>3)&1) + ((k>>2)&1)
__device__ __forceinline__ int quad_off(int n, int k) {
    return 16 * (((k >> 4)) ^ (n & 3)) + 4 * (k & 3) + 2 * ((k >> 3) & 1) + ((k >> 2) & 1);
}

// mma.sync m16n8k8 tf32: D += A*B (fp32 accum)
__device__ __forceinline__ void mma8(float* c, uint32_t a0, uint32_t a1, uint32_t a2, uint32_t a3,
                                     uint32_t b0, uint32_t b1) {
    asm volatile("mma.sync.aligned.m16n8k8.row.col.f32.tf32.tf32.f32 "
                 "{%0,%1,%2,%3}, {%4,%5,%6,%7}, {%8,%9}, {%0,%1,%2,%3};"
                 : "+f"(c[0]), "+f"(c[1]), "+f"(c[2]), "+f"(c[3])
                 : "r"(a0), "r"(a1), "r"(a2), "r"(a3), "r"(b0), "r"(b1));
}

__device__ __forceinline__ float4 shfl4(float4 v, int src) {
    float4 r;
    r.x = __shfl_sync(0xffffffffu, v.x, src);
    r.y = __shfl_sync(0xffffffffu, v.y, src);
    r.z = __shfl_sync(0xffffffffu, v.z, src);
    r.w = __shfl_sync(0xffffffffu, v.w, src);
    return r;
}

// ---------------- merged setup kernel ----------------------------------------
// blocks [0,128)=W_rec image (block=k, thread=n: coalesced reads),
// [128,256)=W_in image, [256,299)=wkq (smem-tiled), 299=bias0,
// [300, 300+lut_blocks)=lut fill. All parts independent.
#define SETUP_SMEM (128 * 133 * 4)   // 68096
__global__ void __launch_bounds__(384, 2)
k_setup(const float* __restrict__ bin, const float* __restrict__ brec,
        const float* __restrict__ wk,  const float* __restrict__ wq,
        const float* __restrict__ Wrec, const float* __restrict__ Win,
        const int* __restrict__ paths, const int* __restrict__ idx,
        const int* __restrict__ seqs, int T) {
    extern __shared__ float wk_s[];   // 128*133 (wkq branch only)
    int bid = blockIdx.x;
    int tid = threadIdx.x;

    if (bid < 256) {
        // W image: block = k (0..127), thread = n (0..383). Coalesced read of
        // src[k*G3 + n]; scattered 4B store (fire-and-forget).
        const float* src = (bid < 128) ? Wrec : Win;
        uint32_t*    dst = (bid < 128) ? g_wrec : g_win;
        int k = bid & 127;
        dst[tid * 128 + quad_off(tid, k)] = f2tf32(src[k * G3 + tid]);
    } else if (bid < 299) {
        // wkq: stage wk transposed in smem (conflict-free, coalesced read),
        // then 128-MAC loops from smem + broadcast wq.
        for (int i2 = tid; i2 < D_ * D_; i2 += 384) {
            int d = i2 >> 7, e = i2 & 127;
            wk_s[e * 133 + d] = wk[i2];
        }
        __syncthreads();
        int i = (bid - 256) * 384 + tid;
        if (i < D_ * D_) {
            int dp = i >> 7, d = i & 127;
            float acc = 0.f;
            #pragma unroll 4
            for (int e = 0; e < D_; e++) acc += wk_s[e * 133 + d] * wq[dp * D_ + e];
            g_wkqT[dp * D_ + d] = acc;
        }
    } else if (bid == 299) {
        // zero-input row of g_proj (interleaved); bz,br folded, bh separate
        int e = tid & 127, g = tid >> 7;   // g in 0..2
        float v = bin[g * 128 + e];
        if (g < 2) v += brec[g * 128 + e];
        g_proj[(size_t)B_ * E_ * PROJ_STRIDE + e * 4 + g] = v;
    } else {
        int j = (bid - 300) * 384 + tid;
        if (j < T) g_lut[idx[j] * LMAX + seqs[j]] = paths[j] + 1;
    }
}

// ---------------- proj via tf32 mma ------------------------------------------
// 64 rows/CTA, 512 threads (16 warps). Warp w owns e-cols [8w,8w+8) of all 3 gates.
#define PROJ_SMEM ((G3 * D_ + 64 * D_) * 4)   // 229376
__global__ void __launch_bounds__(512, 1)
k_proj_mma(const float* __restrict__ inp, const float* __restrict__ bin,
           const float* __restrict__ brec) {
    extern __shared__ float sm[];
    uint32_t* Wb = (uint32_t*)sm;         // 49152 words
    uint32_t* Ab = Wb + G3 * D_;          // 64*128 words

    int tid  = threadIdx.x;
    int w    = tid >> 5, lane = tid & 31;
    int gid  = lane >> 2, tig = lane & 3;
    int xorb = gid & 3;
    int row0 = blockIdx.x * 64;

    {   // stage W image + input rows (tf32, quad-fragment layout)
        const float4* s = (const float4*)g_win;
        float4*       d = (float4*)Wb;
        #pragma unroll 4
        for (int i = tid; i < G3 * D_ / 4; i += 512) d[i] = s[i];
        const float* ip = inp + (size_t)row0 * DIN_;
        for (int i = tid; i < 64 * DIN_; i += 512) {
            int r = i >> 7, k = i & 127;
            Ab[r * 128 + quad_off(r, k)] = f2tf32(ip[i]);
        }
    }
    __syncthreads();

    const int ecol = 8 * w + 2 * tig;
    float2 bias[3];
    #pragma unroll
    for (int g = 0; g < 3; g++) {
        int n = g * 128 + ecol;
        bias[g] = *(const float2*)(bin + n);
        if (g < 2) {
            float2 bb2 = *(const float2*)(brec + n);
            bias[g].x += bb2.x; bias[g].y += bb2.y;
        }
    }

    float acc[4][3][4];
    #pragma unroll
    for (int a = 0; a < 4; a++)
        for (int q = 0; q < 3; q++)
            for (int c = 0; c < 4; c++) acc[a][q][c] = 0.f;

    #pragma unroll
    for (int kg = 0; kg < 8; kg++) {
        int koff = 16 * (kg ^ xorb) + 4 * tig;
        uint4 bf[3];
        #pragma unroll
        for (int g = 0; g < 3; g++)
            bf[g] = *(const uint4*)(Wb + (g * 128 + 8 * w + gid) * 128 + koff);
        #pragma unroll
        for (int mt = 0; mt < 4; mt++) {
            int r = 16 * mt + gid;
            uint4 alo = *(const uint4*)(Ab + r * 128 + koff);
            uint4 ahi = *(const uint4*)(Ab + (r + 8) * 128 + koff);
            #pragma unroll
            for (int g = 0; g < 3; g++) {
                mma8(acc[mt][g], alo.x, ahi.x, alo.y, ahi.y, bf[g].x, bf[g].y);
                mma8(acc[mt][g], alo.z, ahi.z, alo.w, ahi.w, bf[g].z, bf[g].w);
            }
        }
    }

    #pragma unroll
    for (int mt = 0; mt < 4; mt++)
        #pragma unroll
        for (int hf = 0; hf < 2; hf++) {
            int r = 16 * mt + 8 * hf + gid;
            float* grow = g_proj + (size_t)(row0 + r) * PROJ_STRIDE;
            *(float4*)(grow + ecol * 4) =
                make_float4(acc[mt][0][hf * 2] + bias[0].x,
                            acc[mt][1][hf * 2] + bias[1].x,
                            acc[mt][2][hf * 2] + bias[2].x, 0.f);
            *(float4*)(grow + ecol * 4 + 4) =
                make_float4(acc[mt][0][hf * 2 + 1] + bias[0].y,
                            acc[mt][1][hf * 2 + 1] + bias[1].y,
                            acc[mt][2][hf * 2 + 1] + bias[2].y, 0.f);
        }
}

// ---------------- fused tf32-HMMA GRU + shfl4 attention (R9 config) -----------
// 32 rows/CTA (grid 1024), 512 threads (16 warps). Warp w owns e-cols [8w,8w+8)
// of all 3 gates; 2 m-tiles. Double-buffered tf32 h, 1 barrier/step.
#define GRU_ROWS 32
#define GRU_SMEM (G3 * D_ * 4 + 2 * GRU_ROWS * D_ * 4 + GRU_ROWS * LMAX * 2)  // 230400
__global__ void __launch_bounds__(512, 1)
k_gru_fused(const float* __restrict__ brec, const float* __restrict__ wv,
            float* __restrict__ out) {
    extern __shared__ float sm[];
    uint32_t*  Wb   = (uint32_t*)sm;                  // 49152 words
    uint32_t*  hb0  = Wb + G3 * D_;                   // 32*128 words (tf32 bits of h)
    uint32_t*  hb1  = hb0 + GRU_ROWS * D_;            // 32*128 words
    uint16_t*  prow = (uint16_t*)(hb1 + GRU_ROWS * D_);  // 32*16 u16

    int tid  = threadIdx.x;
    int w    = tid >> 5, lane = tid & 31;
    int gid  = lane >> 2, tig = lane & 3;
    int xorb = gid & 3;
    int n0   = blockIdx.x * GRU_ROWS;
    int bb   = n0 >> 11;                // batch index (32 | 2048)
    int p0   = n0 & (P_ - 1);

    {   // stage W image + gather row ids (u16; 16384 = zero row)
        const float4* s = (const float4*)g_wrec;
        float4*       d = (float4*)Wb;
        #pragma unroll 4
        for (int i = tid; i < G3 * D_ / 4; i += 512) d[i] = s[i];
        if (tid < GRU_ROWS * LMAX) {
            int e1 = g_lut[p0 * LMAX + tid];
            prow[tid] = (uint16_t)(e1 > 0 ? (bb * E_ + e1 - 1) : B_ * E_);
        }
    }
    __syncthreads();

    const int ecol = 8 * w + 2 * tig;
    float bh0 = brec[256 + ecol];
    float bh1 = brec[256 + ecol + 1];

    float hold[2][2][2];   // [mt][hf][p]
    #pragma unroll
    for (int a = 0; a < 2; a++)
        for (int b = 0; b < 2; b++)
            for (int c = 0; c < 2; c++) hold[a][b][c] = 0.f;

    // h write word offsets (cols ecol, ecol+1) in quad layout
    const int wsw0 = quad_off(gid, ecol);
    const int wsw1 = quad_off(gid, ecol + 1);

    for (int t = 0; t < LMAX; t++) {
        uint32_t* hcur = (t & 1) ? hb1 : hb0;
        uint32_t* hnxt = (t & 1) ? hb0 : hb1;

        // ---- prefetch x-gates (interleaved proj: one float4 per column) ----
        float4 xq[2][2][2];   // [mt][hf][col p]
        #pragma unroll
        for (int mt = 0; mt < 2; mt++)
            #pragma unroll
            for (int hf = 0; hf < 2; hf++) {
                int r = 16 * mt + 8 * hf + gid;
                const float4* xp = (const float4*)(g_proj + (size_t)prow[r * LMAX + t] * PROJ_STRIDE);
                xq[mt][hf][0] = xp[ecol];
                xq[mt][hf][1] = xp[ecol + 1];
            }

        // ---- gates = h @ W_rec  (tf32 mma, quad LDS.128 fragments) ----
        float acc[2][3][4];
        #pragma unroll
        for (int a = 0; a < 2; a++)
            for (int q = 0; q < 3; q++)
                for (int c = 0; c < 4; c++) acc[a][q][c] = 0.f;

        if (t > 0) {   // h==0 at t=0
            #pragma unroll
            for (int kg = 0; kg < 8; kg++) {
                int koff = 16 * (kg ^ xorb) + 4 * tig;
                uint4 bf[3];
                #pragma unroll
                for (int g = 0; g < 3; g++)
                    bf[g] = *(const uint4*)(Wb + (g * 128 + 8 * w + gid) * 128 + koff);
                #pragma unroll
                for (int mt = 0; mt < 2; mt++) {
                    int r = 16 * mt + gid;
                    uint4 alo = *(const uint4*)(hcur + r * 128 + koff);
                    uint4 ahi = *(const uint4*)(hcur + (r + 8) * 128 + koff);
                    #pragma unroll
                    for (int g = 0; g < 3; g++) {
                        mma8(acc[mt][g], alo.x, ahi.x, alo.y, ahi.y, bf[g].x, bf[g].y);
                        mma8(acc[mt][g], alo.z, ahi.z, alo.w, ahi.w, bf[g].z, bf[g].w);
                    }
                }
            }
        }

        // ---- elementwise GRU update (writes the OTHER buffer) ----
        #pragma unroll
        for (int mt = 0; mt < 2; mt++)
            #pragma unroll
            for (int hf = 0; hf < 2; hf++) {
                int r = 16 * mt + 8 * hf + gid;
                float hn[2];
                #pragma unroll
                for (int p = 0; p < 2; p++) {
                    float4 xc = xq[mt][hf][p];
                    float bhv = p ? bh1 : bh0;
                    float z  = sigf(xc.x + acc[mt][0][hf * 2 + p]);
                    float rr = sigf(xc.y + acc[mt][1][hf * 2 + p]);
                    float hc = tanha(xc.z + rr * (acc[mt][2][hf * 2 + p] + bhv));
                    float hv = z * hold[mt][hf][p] + (1.0f - z) * hc;
                    hold[mt][hf][p] = hv;
                    hn[p] = hv;
                }
                if (t < LMAX - 1) {
                    hnxt[r * 128 + wsw0] = f2tf32(hn[0]);
                    hnxt[r * 128 + wsw1] = f2tf32(hn[1]);
                }
                *(float2*)(g_hs + (size_t)(n0 + r) * (LMAX * D_) + t * D_ + ecol)
                    = make_float2(hn[0], hn[1]);
            }
        __syncthreads();
    }

    // ============ fused attention epilogue (shfl4, 2 rows/warp) ============
    float* wkqS = sm;           // 16384 words
    float* wvS  = sm + 16384;   // 16384 words
    {
        const float4* s4 = (const float4*)g_wkqT;
        const float4* t4 = (const float4*)wv;
        float4*       a4 = (float4*)wkqS;
        float4*       b4 = (float4*)wvS;
        for (int i = tid; i < 4096; i += 512) { a4[i] = s4[i]; b4[i] = t4[i]; }
    }
    __syncthreads();

    const float4* wkq4 = (const float4*)wkqS;
    const float4* wv4  = (const float4*)wvS;

    #pragma unroll 1
    for (int rr = 0; rr < 2; rr++) {
        int row = n0 + 2 * w + rr;
        float4 hrow[LMAX];
        const float4* g4 = (const float4*)(g_hs + (size_t)row * (LMAX * D_));
        #pragma unroll
        for (int l = 0; l < LMAX; l++) hrow[l] = g4[l * 32 + lane];

        float4 last = hrow[LMAX - 1];
        float4 m = make_float4(0.f, 0.f, 0.f, 0.f);
        #pragma unroll 4
        for (int dg = 0; dg < 32; dg++) {
            float4 lv = shfl4(last, dg);
            m.x = fmaf(lv.x, wkq4[(4 * dg + 0) * 32 + lane].x, m.x);
            m.y = fmaf(lv.x, wkq4[(4 * dg + 0) * 32 + lane].y, m.y);
            m.z = fmaf(lv.x, wkq4[(4 * dg + 0) * 32 + lane].z, m.z);
            m.w = fmaf(lv.x, wkq4[(4 * dg + 0) * 32 + lane].w, m.w);
            m.x = fmaf(lv.y, wkq4[(4 * dg + 1) * 32 + lane].x, m.x);
            m.y = fmaf(lv.y, wkq4[(4 * dg + 1) * 32 + lane].y, m.y);
            m.z = fmaf(lv.y, wkq4[(4 * dg + 1) * 32 + lane].z, m.z);
            m.w = fmaf(lv.y, wkq4[(4 * dg + 1) * 32 + lane].w, m.w);
            m.x = fmaf(lv.z, wkq4[(4 * dg + 2) * 32 + lane].x, m.x);
            m.y = fmaf(lv.z, wkq4[(4 * dg + 2) * 32 + lane].y, m.y);
            m.z = fmaf(lv.z, wkq4[(4 * dg + 2) * 32 + lane].z, m.z);
            m.w = fmaf(lv.z, wkq4[(4 * dg + 2) * 32 + lane].w, m.w);
            m.x = fmaf(lv.w, wkq4[(4 * dg + 3) * 32 + lane].x, m.x);
            m.y = fmaf(lv.w, wkq4[(4 * dg + 3) * 32 + lane].y, m.y);
            m.z = fmaf(lv.w, wkq4[(4 * dg + 3) * 32 + lane].z, m.z);
            m.w = fmaf(lv.w, wkq4[(4 * dg + 3) * 32 + lane].w, m.w);
        }

        float4 u = make_float4(0.f, 0.f, 0.f, 0.f);
        #pragma unroll
        for (int l = 0; l < LMAX; l++) {
            float4 h4 = hrow[l];
            float  pp = m.x * h4.x + m.y * h4.y + m.z * h4.z + m.w * h4.w;
            #pragma unroll
            for (int o = 16; o > 0; o >>= 1) pp += __shfl_xor_sync(0xffffffffu, pp, o);
            u.x = fmaf(pp, h4.x, u.x); u.y = fmaf(pp, h4.y, u.y);
            u.z = fmaf(pp, h4.z, u.z); u.w = fmaf(pp, h4.w, u.w);
        }

        float4 c = make_float4(0.f, 0.f, 0.f, 0.f);
        #pragma unroll 4
        for (int dg = 0; dg < 32; dg++) {
            float4 uv = shfl4(u, dg);
            c.x = fmaf(uv.x, wv4[(4 * dg + 0) * 32 + lane].x, c.x);
            c.y = fmaf(uv.x, wv4[(4 * dg + 0) * 32 + lane].y, c.y);
            c.z = fmaf(uv.x, wv4[(4 * dg + 0) * 32 + lane].z, c.z);
            c.w = fmaf(uv.x, wv4[(4 * dg + 0) * 32 + lane].w, c.w);
            c.x = fmaf(uv.y, wv4[(4 * dg + 1) * 32 + lane].x, c.x);
            c.y = fmaf(uv.y, wv4[(4 * dg + 1) * 32 + lane].y, c.y);
            c.z = fmaf(uv.y, wv4[(4 * dg + 1) * 32 + lane].z, c.z);
            c.w = fmaf(uv.y, wv4[(4 * dg + 1) * 32 + lane].w, c.w);
            c.x = fmaf(uv.z, wv4[(4 * dg + 2) * 32 + lane].x, c.x);
            c.y = fmaf(uv.z, wv4[(4 * dg + 2) * 32 + lane].y, c.y);
            c.z = fmaf(uv.z, wv4[(4 * dg + 2) * 32 + lane].z, c.z);
            c.w = fmaf(uv.z, wv4[(4 * dg + 2) * 32 + lane].w, c.w);
            c.x = fmaf(uv.w, wv4[(4 * dg + 3) * 32 + lane].x, c.x);
            c.y = fmaf(uv.w, wv4[(4 * dg + 3) * 32 + lane].y, c.y);
            c.z = fmaf(uv.w, wv4[(4 * dg + 3) * 32 + lane].z, c.z);
            c.w = fmaf(uv.w, wv4[(4 * dg + 3) * 32 + lane].w, c.w);
        }
        *(float4*)&out[(size_t)row * 128 + 4 * lane] = c;
    }
}

// ---------------- launch -----------------------------------------------------
extern "C" void kernel_launch(void* const* d_in, const int* in_sizes, int n_in,
                              void* d_out, int out_size) {
    const float* inputs = (const float*)d_in[0];
    const float* W_in   = (const float*)d_in[1];
    const float* W_rec  = (const float*)d_in[2];
    const float* b_in   = (const float*)d_in[3];
    const float* b_rec  = (const float*)d_in[4];
    const float* wq     = (const float*)d_in[5];
    const float* wk     = (const float*)d_in[6];
    const float* wv     = (const float*)d_in[7];
    const int*   paths  = (const int*)d_in[8];
    const int*   idx    = (const int*)d_in[9];
    const int*   seqs   = (const int*)d_in[10];
    int T = in_sizes[8];

    cudaFuncSetAttribute(k_setup,     cudaFuncAttributeMaxDynamicSharedMemorySize, SETUP_SMEM);
    cudaFuncSetAttribute(k_proj_mma,  cudaFuncAttributeMaxDynamicSharedMemorySize, PROJ_SMEM);
    cudaFuncSetAttribute(k_gru_fused, cudaFuncAttributeMaxDynamicSharedMemorySize, GRU_SMEM);

    int lut_blocks = (T + 383) / 384;
    k_setup<<<300 + lut_blocks, 384, SETUP_SMEM>>>(b_in, b_rec, wk, wq, W_rec, W_in,
                                                   paths, idx, seqs, T);
    k_proj_mma<<<(B_ * E_) / 64, 512, PROJ_SMEM>>>(inputs, b_in, b_rec);
    k_gru_fused<<<(B_ * P_) / GRU_ROWS, 512, GRU_SMEM>>>(b_rec, wv, (float*)d_out);
}

// round 15
// speedup vs baseline: 1.2635x; 1.0922x over previous
#include <cuda_runtime.h>
#include <math.h>
#include <stdint.h>

// Problem constants (fixed by the reference)
#define B_   16
#define E_   1024
#define DIN_ 128
#define P_   2048
#define D_   128
#define LMAX 16
#define G3   384   // 3*D
#define PROJ_STRIDE 512   // gate-interleaved proj row: [e*4 + {z,r,h,pad}]

// ---------------- scratch (device globals: no allocations allowed) ---------
__device__ int      g_lut[P_ * LMAX];                          // path+1 per (p,t), 0 if empty (BSS zero)
__device__ float    g_proj[((size_t)B_ * E_ + 1) * PROJ_STRIDE];  // interleaved proj; row 16384 = zero row
__device__ float    g_wkqT[D_ * D_];                           // g_wkqT[dp*128+d] = (WkWq^T)[d][dp]
__device__ float    g_hs[(size_t)B_ * P_ * LMAX * D_];         // GRU hidden states (fp32)
__device__ uint32_t g_wrec[G3 * D_];                           // W_rec^T tf32 quad-fragment image
__device__ uint32_t g_win[G3 * D_];                            // W_in^T  tf32 quad-fragment image

__device__ __forceinline__ float tanha(float x) {
    float r; asm("tanh.approx.f32 %0, %1;" : "=f"(r) : "f"(x)); return r;
}
__device__ __forceinline__ float sigf(float x) { return fmaf(tanha(0.5f * x), 0.5f, 0.5f); }

__device__ __forceinline__ uint32_t f2tf32(float v) {
    uint32_t r;
    asm("cvt.rna.tf32.f32 %0, %1;" : "=r"(r) : "f"(v));
    return r;
}

// quad-fragment word offset within a 128-word row image:
//   off(n,k) = 16*((k>>4)^(n&3)) + 4*(k&3) + 2*((k>>3)&1) + ((k>>2)&1)
__device__ __forceinline__ int quad_off(int n, int k) {
    return 16 * (((k >> 4)) ^ (n & 3)) + 4 * (k & 3) + 2 * ((k >> 3) & 1) + ((k >> 2) & 1);
}

// mma.sync m16n8k8 tf32: D += A*B (fp32 accum)
__device__ __forceinline__ void mma8(float* c, uint32_t a0, uint32_t a1, uint32_t a2, uint32_t a3,
                                     uint32_t b0, uint32_t b1) {
    asm volatile("mma.sync.aligned.m16n8k8.row.col.f32.tf32.tf32.f32 "
                 "{%0,%1,%2,%3}, {%4,%5,%6,%7}, {%8,%9}, {%0,%1,%2,%3};"
                 : "+f"(c[0]), "+f"(c[1]), "+f"(c[2]), "+f"(c[3])
                 : "r"(a0), "r"(a1), "r"(a2), "r"(a3), "r"(b0), "r"(b1));
}

// ---------------- merged setup kernel ----------------------------------------
// blocks [0,128)=W_rec image (block=k, thread=n: coalesced reads),
// [128,256)=W_in image, [256,299)=wkq (smem-tiled), 299=bias0,
// [300, 300+lut_blocks)=lut fill. All parts independent.
#define SETUP_SMEM (128 * 133 * 4)   // 68096
__global__ void __launch_bounds__(384, 2)
k_setup(const float* __restrict__ bin, const float* __restrict__ brec,
        const float* __restrict__ wk,  const float* __restrict__ wq,
        const float* __restrict__ Wrec, const float* __restrict__ Win,
        const int* __restrict__ paths, const int* __restrict__ idx,
        const int* __restrict__ seqs, int T) {
    extern __shared__ float wk_s[];   // 128*133 (wkq branch only)
    int bid = blockIdx.x;
    int tid = threadIdx.x;

    if (bid < 256) {
        // W image: block = k (0..127), thread = n (0..383). Coalesced read of
        // src[k*G3 + n]; scattered 4B store (fire-and-forget).
        const float* src = (bid < 128) ? Wrec : Win;
        uint32_t*    dst = (bid < 128) ? g_wrec : g_win;
        int k = bid & 127;
        dst[tid * 128 + quad_off(tid, k)] = f2tf32(src[k * G3 + tid]);
    } else if (bid < 299) {
        // wkq: stage wk transposed in smem (conflict-free, coalesced read),
        // then 128-MAC loops from smem + broadcast wq.
        for (int i2 = tid; i2 < D_ * D_; i2 += 384) {
            int d = i2 >> 7, e = i2 & 127;
            wk_s[e * 133 + d] = wk[i2];
        }
        __syncthreads();
        int i = (bid - 256) * 384 + tid;
        if (i < D_ * D_) {
            int dp = i >> 7, d = i & 127;
            float acc = 0.f;
            #pragma unroll 4
            for (int e = 0; e < D_; e++) acc += wk_s[e * 133 + d] * wq[dp * D_ + e];
            g_wkqT[dp * D_ + d] = acc;
        }
    } else if (bid == 299) {
        // zero-input row of g_proj (interleaved); bz,br folded, bh separate
        int e = tid & 127, g = tid >> 7;   // g in 0..2
        float v = bin[g * 128 + e];
        if (g < 2) v += brec[g * 128 + e];
        g_proj[(size_t)B_ * E_ * PROJ_STRIDE + e * 4 + g] = v;
    } else {
        int j = (bid - 300) * 384 + tid;
        if (j < T) g_lut[idx[j] * LMAX + seqs[j]] = paths[j] + 1;
    }
}

// ---------------- proj via tf32 mma ------------------------------------------
// 64 rows/CTA, 512 threads (16 warps). Warp w owns e-cols [8w,8w+8) of all 3 gates.
#define PROJ_SMEM ((G3 * D_ + 64 * D_) * 4)   // 229376
__global__ void __launch_bounds__(512, 1)
k_proj_mma(const float* __restrict__ inp, const float* __restrict__ bin,
           const float* __restrict__ brec) {
    extern __shared__ float sm[];
    uint32_t* Wb = (uint32_t*)sm;         // 49152 words
    uint32_t* Ab = Wb + G3 * D_;          // 64*128 words

    int tid  = threadIdx.x;
    int w    = tid >> 5, lane = tid & 31;
    int gid  = lane >> 2, tig = lane & 3;
    int xorb = gid & 3;
    int row0 = blockIdx.x * 64;

    {   // stage W image + input rows (tf32, quad-fragment layout)
        const float4* s = (const float4*)g_win;
        float4*       d = (float4*)Wb;
        #pragma unroll 4
        for (int i = tid; i < G3 * D_ / 4; i += 512) d[i] = s[i];
        const float* ip = inp + (size_t)row0 * DIN_;
        for (int i = tid; i < 64 * DIN_; i += 512) {
            int r = i >> 7, k = i & 127;
            Ab[r * 128 + quad_off(r, k)] = f2tf32(ip[i]);
        }
    }
    __syncthreads();

    const int ecol = 8 * w + 2 * tig;
    float2 bias[3];
    #pragma unroll
    for (int g = 0; g < 3; g++) {
        int n = g * 128 + ecol;
        bias[g] = *(const float2*)(bin + n);
        if (g < 2) {
            float2 bb2 = *(const float2*)(brec + n);
            bias[g].x += bb2.x; bias[g].y += bb2.y;
        }
    }

    float acc[4][3][4];
    #pragma unroll
    for (int a = 0; a < 4; a++)
        for (int q = 0; q < 3; q++)
            for (int c = 0; c < 4; c++) acc[a][q][c] = 0.f;

    #pragma unroll
    for (int kg = 0; kg < 8; kg++) {
        int koff = 16 * (kg ^ xorb) + 4 * tig;
        uint4 bf[3];
        #pragma unroll
        for (int g = 0; g < 3; g++)
            bf[g] = *(const uint4*)(Wb + (g * 128 + 8 * w + gid) * 128 + koff);
        #pragma unroll
        for (int mt = 0; mt < 4; mt++) {
            int r = 16 * mt + gid;
            uint4 alo = *(const uint4*)(Ab + r * 128 + koff);
            uint4 ahi = *(const uint4*)(Ab + (r + 8) * 128 + koff);
            #pragma unroll
            for (int g = 0; g < 3; g++) {
                mma8(acc[mt][g], alo.x, ahi.x, alo.y, ahi.y, bf[g].x, bf[g].y);
                mma8(acc[mt][g], alo.z, ahi.z, alo.w, ahi.w, bf[g].z, bf[g].w);
            }
        }
    }

    #pragma unroll
    for (int mt = 0; mt < 4; mt++)
        #pragma unroll
        for (int hf = 0; hf < 2; hf++) {
            int r = 16 * mt + 8 * hf + gid;
            float* grow = g_proj + (size_t)(row0 + r) * PROJ_STRIDE;
            *(float4*)(grow + ecol * 4) =
                make_float4(acc[mt][0][hf * 2] + bias[0].x,
                            acc[mt][1][hf * 2] + bias[1].x,
                            acc[mt][2][hf * 2] + bias[2].x, 0.f);
            *(float4*)(grow + ecol * 4 + 4) =
                make_float4(acc[mt][0][hf * 2 + 1] + bias[0].y,
                            acc[mt][1][hf * 2 + 1] + bias[1].y,
                            acc[mt][2][hf * 2 + 1] + bias[2].y, 0.f);
        }
}

// ---------------- fused tf32-HMMA GRU + tensor-core attention -----------------
// 32 rows/CTA (grid 1024), 512 threads (16 warps). Warp w owns e-cols [8w,8w+8)
// of all 3 gates; 2 m-tiles. Double-buffered tf32 h, 1 barrier/step.
// Epilogue: m = last@M and ctx = u@Wv as 32x128x128 tf32-mma GEMMs; only the
// per-row att/u reduction stays scalar.
#define GRU_ROWS 32
#define GRU_SMEM (G3 * D_ * 4 + 2 * GRU_ROWS * D_ * 4 + GRU_ROWS * LMAX * 2)  // 230400
__global__ void __launch_bounds__(512, 1)
k_gru_fused(const float* __restrict__ brec, const float* __restrict__ wv,
            float* __restrict__ out) {
    extern __shared__ float sm[];
    uint32_t*  Wb   = (uint32_t*)sm;                  // 49152 words
    uint32_t*  hb0  = Wb + G3 * D_;                   // 32*128 words (tf32 bits of h)
    uint32_t*  hb1  = hb0 + GRU_ROWS * D_;            // 32*128 words
    uint16_t*  prow = (uint16_t*)(hb1 + GRU_ROWS * D_);  // 32*16 u16

    int tid  = threadIdx.x;
    int w    = tid >> 5, lane = tid & 31;
    int gid  = lane >> 2, tig = lane & 3;
    int xorb = gid & 3;
    int n0   = blockIdx.x * GRU_ROWS;
    int bb   = n0 >> 11;                // batch index (32 | 2048)
    int p0   = n0 & (P_ - 1);

    {   // stage W image + gather row ids (u16; 16384 = zero row)
        const float4* s = (const float4*)g_wrec;
        float4*       d = (float4*)Wb;
        #pragma unroll 4
        for (int i = tid; i < G3 * D_ / 4; i += 512) d[i] = s[i];
        if (tid < GRU_ROWS * LMAX) {
            int e1 = g_lut[p0 * LMAX + tid];
            prow[tid] = (uint16_t)(e1 > 0 ? (bb * E_ + e1 - 1) : B_ * E_);
        }
    }
    __syncthreads();

    const int ecol = 8 * w + 2 * tig;
    float bh0 = brec[256 + ecol];
    float bh1 = brec[256 + ecol + 1];

    float hold[2][2][2];   // [mt][hf][p]
    #pragma unroll
    for (int a = 0; a < 2; a++)
        for (int b = 0; b < 2; b++)
            for (int c = 0; c < 2; c++) hold[a][b][c] = 0.f;

    // h write word offsets (cols ecol, ecol+1) in quad layout
    const int wsw0 = quad_off(gid, ecol);
    const int wsw1 = quad_off(gid, ecol + 1);

    for (int t = 0; t < LMAX; t++) {
        uint32_t* hcur = (t & 1) ? hb1 : hb0;
        uint32_t* hnxt = (t & 1) ? hb0 : hb1;

        // ---- prefetch x-gates (interleaved proj: one float4 per column) ----
        float4 xq[2][2][2];   // [mt][hf][col p]
        #pragma unroll
        for (int mt = 0; mt < 2; mt++)
            #pragma unroll
            for (int hf = 0; hf < 2; hf++) {
                int r = 16 * mt + 8 * hf + gid;
                const float4* xp = (const float4*)(g_proj + (size_t)prow[r * LMAX + t] * PROJ_STRIDE);
                xq[mt][hf][0] = xp[ecol];
                xq[mt][hf][1] = xp[ecol + 1];
            }

        // ---- gates = h @ W_rec  (tf32 mma, quad LDS.128 fragments) ----
        float acc[2][3][4];
        #pragma unroll
        for (int a = 0; a < 2; a++)
            for (int q = 0; q < 3; q++)
                for (int c = 0; c < 4; c++) acc[a][q][c] = 0.f;

        if (t > 0) {   // h==0 at t=0
            #pragma unroll
            for (int kg = 0; kg < 8; kg++) {
                int koff = 16 * (kg ^ xorb) + 4 * tig;
                uint4 bf[3];
                #pragma unroll
                for (int g = 0; g < 3; g++)
                    bf[g] = *(const uint4*)(Wb + (g * 128 + 8 * w + gid) * 128 + koff);
                #pragma unroll
                for (int mt = 0; mt < 2; mt++) {
                    int r = 16 * mt + gid;
                    uint4 alo = *(const uint4*)(hcur + r * 128 + koff);
                    uint4 ahi = *(const uint4*)(hcur + (r + 8) * 128 + koff);
                    #pragma unroll
                    for (int g = 0; g < 3; g++) {
                        mma8(acc[mt][g], alo.x, ahi.x, alo.y, ahi.y, bf[g].x, bf[g].y);
                        mma8(acc[mt][g], alo.z, ahi.z, alo.w, ahi.w, bf[g].z, bf[g].w);
                    }
                }
            }
        }

        // ---- elementwise GRU update (writes the OTHER buffer) ----
        // (t=15 also written: hb0 then holds tf32 "last" for the epilogue GEMMs)
        #pragma unroll
        for (int mt = 0; mt < 2; mt++)
            #pragma unroll
            for (int hf = 0; hf < 2; hf++) {
                int r = 16 * mt + 8 * hf + gid;
                float hn[2];
                #pragma unroll
                for (int p = 0; p < 2; p++) {
                    float4 xc = xq[mt][hf][p];
                    float bhv = p ? bh1 : bh0;
                    float z  = sigf(xc.x + acc[mt][0][hf * 2 + p]);
                    float rr = sigf(xc.y + acc[mt][1][hf * 2 + p]);
                    float hc = tanha(xc.z + rr * (acc[mt][2][hf * 2 + p] + bhv));
                    float hv = z * hold[mt][hf][p] + (1.0f - z) * hc;
                    hold[mt][hf][p] = hv;
                    hn[p] = hv;
                }
                hnxt[r * 128 + wsw0] = f2tf32(hn[0]);
                hnxt[r * 128 + wsw1] = f2tf32(hn[1]);
                *(float2*)(g_hs + (size_t)(n0 + r) * (LMAX * D_) + t * D_ + ecol)
                    = make_float2(hn[0], hn[1]);
            }
        __syncthreads();
    }
    // after t=15: hnxt == hb0 holds tf32 fragments of last = h(15)

    // ============ tensor-core attention epilogue ============
    // Wb reuse: wkqI [0,16384) + wvI [16384,32768) quad images (64KB each).
    // hb1 reuse: mS = 32x128 fp32.
    uint32_t* wkqI = Wb;
    uint32_t* wvI  = Wb + 16384;
    float*    mS   = (float*)hb1;

    // stage both images: coalesced L2 reads, scattered 4B smem writes.
    // B[n][k] for m-GEMM = g_wkqT[k*128+n]; for ctx-GEMM = wv[k*128+n].
    for (int i = tid; i < D_ * D_; i += 512) {
        int k = i >> 7, n = i & 127;
        int off = n * 128 + quad_off(n, k);
        wkqI[off] = f2tf32(g_wkqT[i]);
        wvI [off] = f2tf32(wv[i]);
    }
    __syncthreads();

    // ---- m-GEMM: m[32x128] = last(hb0) @ M. Warp w covers d-cols [8w,8w+8).
    {
        float am[2][4];
        #pragma unroll
        for (int a = 0; a < 2; a++)
            for (int c = 0; c < 4; c++) am[a][c] = 0.f;
        #pragma unroll
        for (int kg = 0; kg < 8; kg++) {
            int koff = 16 * (kg ^ xorb) + 4 * tig;
            uint4 bf = *(const uint4*)(wkqI + (8 * w + gid) * 128 + koff);
            #pragma unroll
            for (int mt = 0; mt < 2; mt++) {
                int r = 16 * mt + gid;
                uint4 alo = *(const uint4*)(hb0 + r * 128 + koff);
                uint4 ahi = *(const uint4*)(hb0 + (r + 8) * 128 + koff);
                mma8(am[mt], alo.x, ahi.x, alo.y, ahi.y, bf.x, bf.y);
                mma8(am[mt], alo.z, ahi.z, alo.w, ahi.w, bf.z, bf.w);
            }
        }
        #pragma unroll
        for (int mt = 0; mt < 2; mt++)
            #pragma unroll
            for (int hf = 0; hf < 2; hf++) {
                int r = 16 * mt + 8 * hf + gid;
                *(float2*)(mS + r * 128 + ecol)
                    = make_float2(am[mt][hf * 2], am[mt][hf * 2 + 1]);
            }
    }
    __syncthreads();

    // ---- att/u per warp (rows 2w, 2w+1): u = sum_l (h_l . m) h_l ----
    float4 uvec[2];
    #pragma unroll
    for (int rr = 0; rr < 2; rr++) {
        int r = 2 * w + rr;
        const float4* g4 = (const float4*)(g_hs + (size_t)(n0 + r) * (LMAX * D_));
        float4 m4 = *(const float4*)(mS + r * 128 + 4 * lane);
        float4 u  = make_float4(0.f, 0.f, 0.f, 0.f);
        #pragma unroll
        for (int l = 0; l < LMAX; l++) {
            float4 h4 = g4[l * 32 + lane];
            float  pp = m4.x * h4.x + m4.y * h4.y + m4.z * h4.z + m4.w * h4.w;
            #pragma unroll
            for (int o = 16; o > 0; o >>= 1) pp += __shfl_xor_sync(0xffffffffu, pp, o);
            u.x = fmaf(pp, h4.x, u.x); u.y = fmaf(pp, h4.y, u.y);
            u.z = fmaf(pp, h4.z, u.z); u.w = fmaf(pp, h4.w, u.w);
        }
        uvec[rr] = u;
    }
    // write u as tf32 quad fragments over hb0 (last no longer needed)
    #pragma unroll
    for (int rr = 0; rr < 2; rr++) {
        int r = 2 * w + rr;
        hb0[r * 128 + quad_off(r, 4 * lane + 0)] = f2tf32(uvec[rr].x);
        hb0[r * 128 + quad_off(r, 4 * lane + 1)] = f2tf32(uvec[rr].y);
        hb0[r * 128 + quad_off(r, 4 * lane + 2)] = f2tf32(uvec[rr].z);
        hb0[r * 128 + quad_off(r, 4 * lane + 3)] = f2tf32(uvec[rr].w);
    }
    __syncthreads();

    // ---- ctx-GEMM: out[32x128] = u(hb0) @ Wv. Warp w covers n-cols [8w,8w+8).
    {
        float ac[2][4];
        #pragma unroll
        for (int a = 0; a < 2; a++)
            for (int c = 0; c < 4; c++) ac[a][c] = 0.f;
        #pragma unroll
        for (int kg = 0; kg < 8; kg++) {
            int koff = 16 * (kg ^ xorb) + 4 * tig;
            uint4 bf = *(const uint4*)(wvI + (8 * w + gid) * 128 + koff);
            #pragma unroll
            for (int mt = 0; mt < 2; mt++) {
                int r = 16 * mt + gid;
                uint4 alo = *(const uint4*)(hb0 + r * 128 + koff);
                uint4 ahi = *(const uint4*)(hb0 + (r + 8) * 128 + koff);
                mma8(ac[mt], alo.x, ahi.x, alo.y, ahi.y, bf.x, bf.y);
                mma8(ac[mt], alo.z, ahi.z, alo.w, ahi.w, bf.z, bf.w);
            }
        }
        #pragma unroll
        for (int mt = 0; mt < 2; mt++)
            #pragma unroll
            for (int hf = 0; hf < 2; hf++) {
                int r = 16 * mt + 8 * hf + gid;
                *(float2*)(out + (size_t)(n0 + r) * 128 + ecol)
                    = make_float2(ac[mt][hf * 2], ac[mt][hf * 2 + 1]);
            }
    }
}

// ---------------- launch -----------------------------------------------------
extern "C" void kernel_launch(void* const* d_in, const int* in_sizes, int n_in,
                              void* d_out, int out_size) {
    const float* inputs = (const float*)d_in[0];
    const float* W_in   = (const float*)d_in[1];
    const float* W_rec  = (const float*)d_in[2];
    const float* b_in   = (const float*)d_in[3];
    const float* b_rec  = (const float*)d_in[4];
    const float* wq     = (const float*)d_in[5];
    const float* wk     = (const float*)d_in[6];
    const float* wv     = (const float*)d_in[7];
    const int*   paths  = (const int*)d_in[8];
    const int*   idx    = (const int*)d_in[9];
    const int*   seqs   = (const int*)d_in[10];
    int T = in_sizes[8];

    cudaFuncSetAttribute(k_setup,     cudaFuncAttributeMaxDynamicSharedMemorySize, SETUP_SMEM);
    cudaFuncSetAttribute(k_proj_mma,  cudaFuncAttributeMaxDynamicSharedMemorySize, PROJ_SMEM);
    cudaFuncSetAttribute(k_gru_fused, cudaFuncAttributeMaxDynamicSharedMemorySize, GRU_SMEM);

    int lut_blocks = (T + 383) / 384;
    k_setup<<<300 + lut_blocks, 384, SETUP_SMEM>>>(b_in, b_rec, wk, wq, W_rec, W_in,
                                                   paths, idx, seqs, T);
    k_proj_mma<<<(B_ * E_) / 64, 512, PROJ_SMEM>>>(inputs, b_in, b_rec);
    k_gru_fused<<<(B_ * P_) / GRU_ROWS, 512, GRU_SMEM>>>(b_rec, wv, (float*)d_out);
}

// round 16
// speedup vs baseline: 1.4179x; 1.1222x over previous
#include <cuda_runtime.h>
#include <math.h>
#include <stdint.h>

// Problem constants (fixed by the reference)
#define B_   16
#define E_   1024
#define DIN_ 128
#define P_   2048
#define D_   128
#define LMAX 16
#define G3   384   // 3*D
#define PROJ_STRIDE 512   // gate-interleaved proj row: [e*4 + {z,r,h,pad}]

// ---------------- scratch (device globals: no allocations allowed) ---------
__device__ int      g_lut[P_ * LMAX];                          // path+1 per (p,t), 0 if empty (BSS zero)
__device__ float    g_proj[((size_t)B_ * E_ + 1) * PROJ_STRIDE];  // interleaved proj; row 16384 = zero row
__device__ float    g_wkqT[D_ * D_];                           // g_wkqT[dp*128+d] = (WkWq^T)[d][dp]
__device__ float    g_hs[(size_t)B_ * P_ * LMAX * D_];         // GRU hidden states (fp32)
__device__ uint32_t g_wrec[G3 * D_];                           // W_rec^T tf32 quad-fragment image
__device__ uint32_t g_win[G3 * D_];                            // W_in^T  tf32 quad-fragment image
__device__ uint32_t g_wkq_img[D_ * D_];                        // M quad image for m-GEMM
__device__ uint32_t g_wv_img[D_ * D_];                         // Wv quad image for ctx-GEMM

__device__ __forceinline__ float tanha(float x) {
    float r; asm("tanh.approx.f32 %0, %1;" : "=f"(r) : "f"(x)); return r;
}
__device__ __forceinline__ float sigf(float x) { return fmaf(tanha(0.5f * x), 0.5f, 0.5f); }

__device__ __forceinline__ uint32_t f2tf32(float v) {
    uint32_t r;
    asm("cvt.rna.tf32.f32 %0, %1;" : "=r"(r) : "f"(v));
    return r;
}

// quad-fragment word offset within a 128-word row image:
//   off(n,k) = 16*((k>>4)^(n&3)) + 4*(k&3) + 2*((k>>3)&1) + ((k>>2)&1)
__device__ __forceinline__ int quad_off(int n, int k) {
    return 16 * (((k >> 4)) ^ (n & 3)) + 4 * (k & 3) + 2 * ((k >> 3) & 1) + ((k >> 2) & 1);
}

// mma.sync m16n8k8 tf32: D += A*B (fp32 accum)
__device__ __forceinline__ void mma8(float* c, uint32_t a0, uint32_t a1, uint32_t a2, uint32_t a3,
                                     uint32_t b0, uint32_t b1) {
    asm volatile("mma.sync.aligned.m16n8k8.row.col.f32.tf32.tf32.f32 "
                 "{%0,%1,%2,%3}, {%4,%5,%6,%7}, {%8,%9}, {%0,%1,%2,%3};"
                 : "+f"(c[0]), "+f"(c[1]), "+f"(c[2]), "+f"(c[3])
                 : "r"(a0), "r"(a1), "r"(a2), "r"(a3), "r"(b0), "r"(b1));
}

// ---------------- merged setup kernel ----------------------------------------
// blocks [0,128)=W_rec image (block=k, thread=n: coalesced reads),
// [128,256)=W_in image, [256,299)=wkq (smem-tiled), 299=bias0,
// [300, 300+lut_blocks)=lut fill. All parts independent.
#define SETUP_SMEM (128 * 133 * 4)   // 68096
__global__ void __launch_bounds__(384, 2)
k_setup(const float* __restrict__ bin, const float* __restrict__ brec,
        const float* __restrict__ wk,  const float* __restrict__ wq,
        const float* __restrict__ Wrec, const float* __restrict__ Win,
        const int* __restrict__ paths, const int* __restrict__ idx,
        const int* __restrict__ seqs, int T) {
    extern __shared__ float wk_s[];   // 128*133 (wkq branch only)
    int bid = blockIdx.x;
    int tid = threadIdx.x;

    if (bid < 256) {
        const float* src = (bid < 128) ? Wrec : Win;
        uint32_t*    dst = (bid < 128) ? g_wrec : g_win;
        int k = bid & 127;
        dst[tid * 128 + quad_off(tid, k)] = f2tf32(src[k * G3 + tid]);
    } else if (bid < 299) {
        for (int i2 = tid; i2 < D_ * D_; i2 += 384) {
            int d = i2 >> 7, e = i2 & 127;
            wk_s[e * 133 + d] = wk[i2];
        }
        __syncthreads();
        int i = (bid - 256) * 384 + tid;
        if (i < D_ * D_) {
            int dp = i >> 7, d = i & 127;
            float acc = 0.f;
            #pragma unroll 4
            for (int e = 0; e < D_; e++) acc += wk_s[e * 133 + d] * wq[dp * D_ + e];
            g_wkqT[dp * D_ + d] = acc;
        }
    } else if (bid == 299) {
        // zero-input row of g_proj (interleaved); bz,br folded, bh separate
        int e = tid & 127, g = tid >> 7;   // g in 0..2
        float v = bin[g * 128 + e];
        if (g < 2) v += brec[g * 128 + e];
        g_proj[(size_t)B_ * E_ * PROJ_STRIDE + e * 4 + g] = v;
    } else {
        int j = (bid - 300) * 384 + tid;
        if (j < T) g_lut[idx[j] * LMAX + seqs[j]] = paths[j] + 1;
    }
}

// ---------------- proj via tf32 mma + epilogue-image build --------------------
// blocks [0,256): proj 64 rows/CTA. blocks 256,257: build g_wkq_img / g_wv_img
// (g_wkqT is ready: k_setup completed before this launch).
#define PROJ_SMEM ((G3 * D_ + 64 * D_) * 4)   // 229376
__global__ void __launch_bounds__(512, 1)
k_proj_mma(const float* __restrict__ inp, const float* __restrict__ bin,
           const float* __restrict__ brec, const float* __restrict__ wv) {
    int tid  = threadIdx.x;

    if (blockIdx.x >= 256) {
        // epilogue image build: image[n*128+quad_off(n,k)] = tf32(src[k*128+n])
        const float* src = (blockIdx.x == 256) ? g_wkqT : wv;
        uint32_t*    dst = (blockIdx.x == 256) ? g_wkq_img : g_wv_img;
        for (int i = tid; i < D_ * D_; i += 512) {
            int k = i >> 7, n = i & 127;
            dst[n * 128 + quad_off(n, k)] = f2tf32(src[i]);
        }
        return;
    }

    extern __shared__ float sm[];
    uint32_t* Wb = (uint32_t*)sm;         // 49152 words
    uint32_t* Ab = Wb + G3 * D_;          // 64*128 words

    int w    = tid >> 5, lane = tid & 31;
    int gid  = lane >> 2, tig = lane & 3;
    int xorb = gid & 3;
    int row0 = blockIdx.x * 64;

    {   // stage W image + input rows (tf32, quad-fragment layout)
        const float4* s = (const float4*)g_win;
        float4*       d = (float4*)Wb;
        #pragma unroll 4
        for (int i = tid; i < G3 * D_ / 4; i += 512) d[i] = s[i];
        const float* ip = inp + (size_t)row0 * DIN_;
        for (int i = tid; i < 64 * DIN_; i += 512) {
            int r = i >> 7, k = i & 127;
            Ab[r * 128 + quad_off(r, k)] = f2tf32(ip[i]);
        }
    }
    __syncthreads();

    const int ecol = 8 * w + 2 * tig;
    float2 bias[3];
    #pragma unroll
    for (int g = 0; g < 3; g++) {
        int n = g * 128 + ecol;
        bias[g] = *(const float2*)(bin + n);
        if (g < 2) {
            float2 bb2 = *(const float2*)(brec + n);
            bias[g].x += bb2.x; bias[g].y += bb2.y;
        }
    }

    float acc[4][3][4];
    #pragma unroll
    for (int a = 0; a < 4; a++)
        for (int q = 0; q < 3; q++)
            for (int c = 0; c < 4; c++) acc[a][q][c] = 0.f;

    #pragma unroll
    for (int kg = 0; kg < 8; kg++) {
        int koff = 16 * (kg ^ xorb) + 4 * tig;
        uint4 bf[3];
        #pragma unroll
        for (int g = 0; g < 3; g++)
            bf[g] = *(const uint4*)(Wb + (g * 128 + 8 * w + gid) * 128 + koff);
        #pragma unroll
        for (int mt = 0; mt < 4; mt++) {
            int r = 16 * mt + gid;
            uint4 alo = *(const uint4*)(Ab + r * 128 + koff);
            uint4 ahi = *(const uint4*)(Ab + (r + 8) * 128 + koff);
            #pragma unroll
            for (int g = 0; g < 3; g++) {
                mma8(acc[mt][g], alo.x, ahi.x, alo.y, ahi.y, bf[g].x, bf[g].y);
                mma8(acc[mt][g], alo.z, ahi.z, alo.w, ahi.w, bf[g].z, bf[g].w);
            }
        }
    }

    #pragma unroll
    for (int mt = 0; mt < 4; mt++)
        #pragma unroll
        for (int hf = 0; hf < 2; hf++) {
            int r = 16 * mt + 8 * hf + gid;
            float* grow = g_proj + (size_t)(row0 + r) * PROJ_STRIDE;
            *(float4*)(grow + ecol * 4) =
                make_float4(acc[mt][0][hf * 2] + bias[0].x,
                            acc[mt][1][hf * 2] + bias[1].x,
                            acc[mt][2][hf * 2] + bias[2].x, 0.f);
            *(float4*)(grow + ecol * 4 + 4) =
                make_float4(acc[mt][0][hf * 2 + 1] + bias[0].y,
                            acc[mt][1][hf * 2 + 1] + bias[1].y,
                            acc[mt][2][hf * 2 + 1] + bias[2].y, 0.f);
        }
}

// ---------------- fused tf32-HMMA GRU + tensor-core attention -----------------
// 32 rows/CTA (grid 1024), 512 threads (16 warps). Warp w owns e-cols [8w,8w+8)
// of all 3 gates; 2 m-tiles. Double-buffered tf32 h, 1 barrier/step.
// g_hs stores use __stcs (evict-first: protect L2-resident g_proj).
#define GRU_ROWS 32
#define GRU_SMEM (G3 * D_ * 4 + 2 * GRU_ROWS * D_ * 4 + GRU_ROWS * LMAX * 2)  // 230400
__global__ void __launch_bounds__(512, 1)
k_gru_fused(const float* __restrict__ brec, float* __restrict__ out) {
    extern __shared__ float sm[];
    uint32_t*  Wb   = (uint32_t*)sm;                  // 49152 words
    uint32_t*  hb0  = Wb + G3 * D_;                   // 32*128 words (tf32 bits of h)
    uint32_t*  hb1  = hb0 + GRU_ROWS * D_;            // 32*128 words
    uint16_t*  prow = (uint16_t*)(hb1 + GRU_ROWS * D_);  // 32*16 u16

    int tid  = threadIdx.x;
    int w    = tid >> 5, lane = tid & 31;
    int gid  = lane >> 2, tig = lane & 3;
    int xorb = gid & 3;
    int n0   = blockIdx.x * GRU_ROWS;
    int bb   = n0 >> 11;                // batch index (32 | 2048)
    int p0   = n0 & (P_ - 1);

    {   // stage W image + gather row ids (u16; 16384 = zero row)
        const float4* s = (const float4*)g_wrec;
        float4*       d = (float4*)Wb;
        #pragma unroll 4
        for (int i = tid; i < G3 * D_ / 4; i += 512) d[i] = s[i];
        if (tid < GRU_ROWS * LMAX) {
            int e1 = g_lut[p0 * LMAX + tid];
            prow[tid] = (uint16_t)(e1 > 0 ? (bb * E_ + e1 - 1) : B_ * E_);
        }
    }
    __syncthreads();

    const int ecol = 8 * w + 2 * tig;
    float bh0 = brec[256 + ecol];
    float bh1 = brec[256 + ecol + 1];

    float hold[2][2][2];   // [mt][hf][p]
    #pragma unroll
    for (int a = 0; a < 2; a++)
        for (int b = 0; b < 2; b++)
            for (int c = 0; c < 2; c++) hold[a][b][c] = 0.f;

    // h write word offsets (cols ecol, ecol+1) in quad layout
    const int wsw0 = quad_off(gid, ecol);
    const int wsw1 = quad_off(gid, ecol + 1);

    for (int t = 0; t < LMAX; t++) {
        uint32_t* hcur = (t & 1) ? hb1 : hb0;
        uint32_t* hnxt = (t & 1) ? hb0 : hb1;

        // ---- prefetch x-gates (interleaved proj: one float4 per column) ----
        float4 xq[2][2][2];   // [mt][hf][col p]
        #pragma unroll
        for (int mt = 0; mt < 2; mt++)
            #pragma unroll
            for (int hf = 0; hf < 2; hf++) {
                int r = 16 * mt + 8 * hf + gid;
                const float4* xp = (const float4*)(g_proj + (size_t)prow[r * LMAX + t] * PROJ_STRIDE);
                xq[mt][hf][0] = xp[ecol];
                xq[mt][hf][1] = xp[ecol + 1];
            }

        // ---- gates = h @ W_rec  (tf32 mma, quad LDS.128 fragments) ----
        float acc[2][3][4];
        #pragma unroll
        for (int a = 0; a < 2; a++)
            for (int q = 0; q < 3; q++)
                for (int c = 0; c < 4; c++) acc[a][q][c] = 0.f;

        if (t > 0) {   // h==0 at t=0
            #pragma unroll
            for (int kg = 0; kg < 8; kg++) {
                int koff = 16 * (kg ^ xorb) + 4 * tig;
                uint4 bf[3];
                #pragma unroll
                for (int g = 0; g < 3; g++)
                    bf[g] = *(const uint4*)(Wb + (g * 128 + 8 * w + gid) * 128 + koff);
                #pragma unroll
                for (int mt = 0; mt < 2; mt++) {
                    int r = 16 * mt + gid;
                    uint4 alo = *(const uint4*)(hcur + r * 128 + koff);
                    uint4 ahi = *(const uint4*)(hcur + (r + 8) * 128 + koff);
                    #pragma unroll
                    for (int g = 0; g < 3; g++) {
                        mma8(acc[mt][g], alo.x, ahi.x, alo.y, ahi.y, bf[g].x, bf[g].y);
                        mma8(acc[mt][g], alo.z, ahi.z, alo.w, ahi.w, bf[g].z, bf[g].w);
                    }
                }
            }
        }

        // ---- elementwise GRU update (writes the OTHER buffer) ----
        // (t=15 also written: hb0 then holds tf32 "last" for the epilogue GEMMs)
        #pragma unroll
        for (int mt = 0; mt < 2; mt++)
            #pragma unroll
            for (int hf = 0; hf < 2; hf++) {
                int r = 16 * mt + 8 * hf + gid;
                float hn[2];
                #pragma unroll
                for (int p = 0; p < 2; p++) {
                    float4 xc = xq[mt][hf][p];
                    float bhv = p ? bh1 : bh0;
                    float z  = sigf(xc.x + acc[mt][0][hf * 2 + p]);
                    float rr = sigf(xc.y + acc[mt][1][hf * 2 + p]);
                    float hc = tanha(xc.z + rr * (acc[mt][2][hf * 2 + p] + bhv));
                    float hv = z * hold[mt][hf][p] + (1.0f - z) * hc;
                    hold[mt][hf][p] = hv;
                    hn[p] = hv;
                }
                hnxt[r * 128 + wsw0] = f2tf32(hn[0]);
                hnxt[r * 128 + wsw1] = f2tf32(hn[1]);
                __stcs((float2*)(g_hs + (size_t)(n0 + r) * (LMAX * D_) + t * D_ + ecol),
                       make_float2(hn[0], hn[1]));
            }
        __syncthreads();
    }
    // after t=15: hb0 holds tf32 fragments of last = h(15)

    // ============ tensor-core attention epilogue ============
    // Wb reuse: wkqI [0,16384) + wvI [16384,32768): float4 copy of prebuilt images.
    uint32_t* wkqI = Wb;
    uint32_t* wvI  = Wb + 16384;
    float*    mS   = (float*)hb1;
    {
        const float4* s1 = (const float4*)g_wkq_img;
        const float4* s2 = (const float4*)g_wv_img;
        float4*       d1 = (float4*)wkqI;
        float4*       d2 = (float4*)wvI;
        #pragma unroll
        for (int i = tid; i < 4096; i += 512) { d1[i] = s1[i]; d2[i] = s2[i]; }
    }
    __syncthreads();

    // ---- m-GEMM: m[32x128] = last(hb0) @ M. Warp w covers d-cols [8w,8w+8).
    {
        float am[2][4];
        #pragma unroll
        for (int a = 0; a < 2; a++)
            for (int c = 0; c < 4; c++) am[a][c] = 0.f;
        #pragma unroll
        for (int kg = 0; kg < 8; kg++) {
            int koff = 16 * (kg ^ xorb) + 4 * tig;
            uint4 bf = *(const uint4*)(wkqI + (8 * w + gid) * 128 + koff);
            #pragma unroll
            for (int mt = 0; mt < 2; mt++) {
                int r = 16 * mt + gid;
                uint4 alo = *(const uint4*)(hb0 + r * 128 + koff);
                uint4 ahi = *(const uint4*)(hb0 + (r + 8) * 128 + koff);
                mma8(am[mt], alo.x, ahi.x, alo.y, ahi.y, bf.x, bf.y);
                mma8(am[mt], alo.z, ahi.z, alo.w, ahi.w, bf.z, bf.w);
            }
        }
        #pragma unroll
        for (int mt = 0; mt < 2; mt++)
            #pragma unroll
            for (int hf = 0; hf < 2; hf++) {
                int r = 16 * mt + 8 * hf + gid;
                *(float2*)(mS + r * 128 + ecol)
                    = make_float2(am[mt][hf * 2], am[mt][hf * 2 + 1]);
            }
    }
    __syncthreads();

    // ---- att/u per warp (rows 2w, 2w+1): u = sum_l (h_l . m) h_l ----
    float4 uvec[2];
    #pragma unroll
    for (int rr = 0; rr < 2; rr++) {
        int r = 2 * w + rr;
        const float4* g4 = (const float4*)(g_hs + (size_t)(n0 + r) * (LMAX * D_));
        float4 m4 = *(const float4*)(mS + r * 128 + 4 * lane);
        float4 u  = make_float4(0.f, 0.f, 0.f, 0.f);
        #pragma unroll
        for (int l = 0; l < LMAX; l++) {
            float4 h4 = __ldcs(g4 + l * 32 + lane);
            float  pp = m4.x * h4.x + m4.y * h4.y + m4.z * h4.z + m4.w * h4.w;
            #pragma unroll
            for (int o = 16; o > 0; o >>= 1) pp += __shfl_xor_sync(0xffffffffu, pp, o);
            u.x = fmaf(pp, h4.x, u.x); u.y = fmaf(pp, h4.y, u.y);
            u.z = fmaf(pp, h4.z, u.z); u.w = fmaf(pp, h4.w, u.w);
        }
        uvec[rr] = u;
    }
    // write u as tf32 quad fragments over hb0 (last no longer needed)
    #pragma unroll
    for (int rr = 0; rr < 2; rr++) {
        int r = 2 * w + rr;
        hb0[r * 128 + quad_off(r, 4 * lane + 0)] = f2tf32(uvec[rr].x);
        hb0[r * 128 + quad_off(r, 4 * lane + 1)] = f2tf32(uvec[rr].y);
        hb0[r * 128 + quad_off(r, 4 * lane + 2)] = f2tf32(uvec[rr].z);
        hb0[r * 128 + quad_off(r, 4 * lane + 3)] = f2tf32(uvec[rr].w);
    }
    __syncthreads();

    // ---- ctx-GEMM: out[32x128] = u(hb0) @ Wv. Warp w covers n-cols [8w,8w+8).
    {
        float ac[2][4];
        #pragma unroll
        for (int a = 0; a < 2; a++)
            for (int c = 0; c < 4; c++) ac[a][c] = 0.f;
        #pragma unroll
        for (int kg = 0; kg < 8; kg++) {
            int koff = 16 * (kg ^ xorb) + 4 * tig;
            uint4 bf = *(const uint4*)(wvI + (8 * w + gid) * 128 + koff);
            #pragma unroll
            for (int mt = 0; mt < 2; mt++) {
                int r = 16 * mt + gid;
                uint4 alo = *(const uint4*)(hb0 + r * 128 + koff);
                uint4 ahi = *(const uint4*)(hb0 + (r + 8) * 128 + koff);
                mma8(ac[mt], alo.x, ahi.x, alo.y, ahi.y, bf.x, bf.y);
                mma8(ac[mt], alo.z, ahi.z, alo.w, ahi.w, bf.z, bf.w);
            }
        }
        #pragma unroll
        for (int mt = 0; mt < 2; mt++)
            #pragma unroll
            for (int hf = 0; hf < 2; hf++) {
                int r = 16 * mt + 8 * hf + gid;
                *(float2*)(out + (size_t)(n0 + r) * 128 + ecol)
                    = make_float2(ac[mt][hf * 2], ac[mt][hf * 2 + 1]);
            }
    }
}

// ---------------- launch -----------------------------------------------------
extern "C" void kernel_launch(void* const* d_in, const int* in_sizes, int n_in,
                              void* d_out, int out_size) {
    const float* inputs = (const float*)d_in[0];
    const float* W_in   = (const float*)d_in[1];
    const float* W_rec  = (const float*)d_in[2];
    const float* b_in   = (const float*)d_in[3];
    const float* b_rec  = (const float*)d_in[4];
    const float* wq     = (const float*)d_in[5];
    const float* wk     = (const float*)d_in[6];
    const float* wv     = (const float*)d_in[7];
    const int*   paths  = (const int*)d_in[8];
    const int*   idx    = (const int*)d_in[9];
    const int*   seqs   = (const int*)d_in[10];
    int T = in_sizes[8];

    cudaFuncSetAttribute(k_setup,     cudaFuncAttributeMaxDynamicSharedMemorySize, SETUP_SMEM);
    cudaFuncSetAttribute(k_proj_mma,  cudaFuncAttributeMaxDynamicSharedMemorySize, PROJ_SMEM);
    cudaFuncSetAttribute(k_gru_fused, cudaFuncAttributeMaxDynamicSharedMemorySize, GRU_SMEM);

    int lut_blocks = (T + 383) / 384;
    k_setup<<<300 + lut_blocks, 384, SETUP_SMEM>>>(b_in, b_rec, wk, wq, W_rec, W_in,
                                                   paths, idx, seqs, T);
    k_proj_mma<<<258, 512, PROJ_SMEM>>>(inputs, b_in, b_rec, wv);
    k_gru_fused<<<(B_ * P_) / GRU_ROWS, 512, GRU_SMEM>>>(b_rec, (float*)d_out);
}